// round 11
// baseline (speedup 1.0000x reference)
#include <cuda_runtime.h>
#include <cstdint>
#include <math.h>

// ---------------- problem constants ----------------
#define BB   2
#define CC   256
#define HH   8
#define HDIM 32
#define TT   16
#define SSQ  512
#define DFFN 1024
#define TSZ  (TT*SSQ)          // 8192
#define ACTN (BB*CC*TSZ)       // 4,194,304 floats
#define NPOS (BB*TSZ)          // 16384 positions

// ---------------- scratch ----------------------------------------------------
__device__ float g_src2[ACTN];
__device__ float g_qk[ACTN];
__device__ float g_qkenc[ACTN];
__device__ float g_qb[ACTN];
__device__ float g_kb[ACTN];
__device__ float g_vb[ACTN];
__device__ float g_vals[ACTN];
__device__ float g_h[BB*DFFN*TSZ];

// pre-rounded + k-permuted weights
__device__ float g_rWq[2*CC*CC];
__device__ float g_rWk[2*CC*CC];
__device__ float g_rWv[2*CC*CC];
__device__ float g_rWo[2*CC*CC];
__device__ float g_rW1[2*DFFN*CC];
__device__ float g_rW2[2*CC*DFFN];

// sparse-attention precompute
__device__ unsigned g_bits[BB*TT*16*SSQ];
__device__ unsigned g_maskw[BB*TT*16];
__device__ int      g_nu[BB*TT];

__device__ __forceinline__ uint32_t f2tf(float x) {
    uint32_t u;
    asm("cvt.rna.tf32.f32 %0, %1;" : "=r"(u) : "f"(x));
    return u;
}
__device__ __forceinline__ float tfr(float x) { return __uint_as_float(f2tf(x)); }

// ---------------- weight prep: tf32-round + within-16-group k-permute --------
#define NGRP_PROJ (2*CC*CC/16)
#define NGRP_FFN  (2*DFFN*CC/16)
#define NGRP_TOT  (4*NGRP_PROJ + 2*NGRP_FFN)

__global__ void prep_weights(const float* __restrict__ Wq, const float* __restrict__ Wk,
                             const float* __restrict__ Wv, const float* __restrict__ Wo,
                             const float* __restrict__ W1, const float* __restrict__ W2,
                             float* __restrict__ rWq, float* __restrict__ rWk,
                             float* __restrict__ rWv, float* __restrict__ rWo,
                             float* __restrict__ rW1, float* __restrict__ rW2)
{
    int g = blockIdx.x * blockDim.x + threadIdx.x;
    if (g >= NGRP_TOT) return;
    const float* src; float* dst; int lg = g;
    if      (g <  NGRP_PROJ)            { src = Wq; dst = rWq; }
    else if (g < 2*NGRP_PROJ)           { src = Wk; dst = rWk; lg = g - NGRP_PROJ; }
    else if (g < 3*NGRP_PROJ)           { src = Wv; dst = rWv; lg = g - 2*NGRP_PROJ; }
    else if (g < 4*NGRP_PROJ)           { src = Wo; dst = rWo; lg = g - 3*NGRP_PROJ; }
    else if (g < 4*NGRP_PROJ+NGRP_FFN)  { src = W1; dst = rW1; lg = g - 4*NGRP_PROJ; }
    else                                { src = W2; dst = rW2; lg = g - 4*NGRP_PROJ - NGRP_FFN; }
    size_t base = (size_t)lg * 16;
    float v[16];
    #pragma unroll
    for (int j = 0; j < 16; j++) v[j] = src[base + j];
    #pragma unroll
    for (int p = 0; p < 16; p++) dst[base + p] = tfr(v[(p & 3) * 4 + (p >> 2)]);
}

// ---------------- gate/mask bit precompute -----------------------------------
__global__ void gate_kernel(const float* __restrict__ coord,
                            const unsigned* __restrict__ mask)
{
    __shared__ float cs[SSQ*3];
    __shared__ unsigned mw[16];
    int bt  = blockIdx.x;
    int wg  = blockIdx.y;
    int tid = threadIdx.x;

    size_t cbase = (size_t)bt * SSQ * 3;
    for (int i = tid; i < SSQ*3; i += 512) cs[i] = coord[cbase + i];
    unsigned mv  = (mask[(size_t)bt*SSQ + tid] != 0u);
    unsigned bal = __ballot_sync(0xffffffffu, mv);
    if ((tid & 31) == 0) mw[tid >> 5] = bal;
    __syncthreads();

    if (wg == 0) {
        if (tid == 0) {
            int nm = 0;
            for (int w = 0; w < 16; w++) nm += __popc(mw[w]);
            g_nu[bt] = SSQ - nm;
        }
        if (tid < 16) g_maskw[bt*16 + tid] = mw[tid];
    }

    float qx = cs[tid*3], qy = cs[tid*3+1], qz = cs[tid*3+2];
    for (int w = wg*4; w < wg*4 + 4; w++) {
        unsigned bits = 0, mk = mw[w];
        #pragma unroll
        for (int bb = 0; bb < 32; bb++) {
            int j = w*32 + bb;
            float dx = qx - cs[j*3], dy = qy - cs[j*3+1], dz = qz - cs[j*3+2];
            float d2 = dx*dx + dy*dy + dz*dz;
            if (d2 < 625.0f && !((mk >> bb) & 1u)) bits |= (1u << bb);
        }
        g_bits[((size_t)bt*16 + w)*SSQ + tid] = bits;
    }
}

// ---------------- fast LayerNorm ---------------------------------------------
template<bool ADDPOS>
__global__ __launch_bounds__(256)
void ln_fast(const float* __restrict__ x,
             const float* __restrict__ gamma,
             const float* __restrict__ beta,
             float* __restrict__ y,
             const float* __restrict__ pos,
             float* __restrict__ y2)
{
    __shared__ float red_s[16][64];
    __shared__ float red_q[16][64];
    __shared__ float mu[64], rs[64];

    const int tid = threadIdx.x;
    const int c16 = tid >> 4;
    const int pg  = tid & 15;
    const int p0  = blockIdx.x * 64 + pg * 4;
    const int b   = p0 / TSZ;
    const int pi  = p0 - b * TSZ;
    const float* xb = x + (size_t)b * CC * TSZ + pi;

    float4 v[16];
    float4 s = make_float4(0.f,0.f,0.f,0.f), q = make_float4(0.f,0.f,0.f,0.f);
    #pragma unroll
    for (int i = 0; i < 16; i++) {
        v[i] = *(const float4*)(xb + (size_t)(c16*16 + i) * TSZ);
        s.x += v[i].x; s.y += v[i].y; s.z += v[i].z; s.w += v[i].w;
        q.x += v[i].x*v[i].x; q.y += v[i].y*v[i].y;
        q.z += v[i].z*v[i].z; q.w += v[i].w*v[i].w;
    }
    red_s[c16][pg*4+0] = s.x; red_s[c16][pg*4+1] = s.y;
    red_s[c16][pg*4+2] = s.z; red_s[c16][pg*4+3] = s.w;
    red_q[c16][pg*4+0] = q.x; red_q[c16][pg*4+1] = q.y;
    red_q[c16][pg*4+2] = q.z; red_q[c16][pg*4+3] = q.w;
    __syncthreads();

    if (tid < 64) {
        float ts = 0.f, tq = 0.f;
        #pragma unroll
        for (int k = 0; k < 16; k++) { ts += red_s[k][tid]; tq += red_q[k][tid]; }
        float m   = ts * (1.0f/CC);
        float var = tq * (1.0f/CC) - m*m;
        mu[tid] = m;
        rs[tid] = rsqrtf(var + 1e-5f);
    }
    __syncthreads();

    float4 m4 = *(const float4*)(mu + pg*4);
    float4 r4 = *(const float4*)(rs + pg*4);
    size_t off = (size_t)b * CC * TSZ + pi;

    #pragma unroll
    for (int i = 0; i < 16; i++) {
        const int c = c16*16 + i;
        const float g = __ldg(&gamma[c]), be = __ldg(&beta[c]);
        float4 nv;
        nv.x = tfr((v[i].x - m4.x) * r4.x * g + be);
        nv.y = tfr((v[i].y - m4.y) * r4.y * g + be);
        nv.z = tfr((v[i].z - m4.z) * r4.z * g + be);
        nv.w = tfr((v[i].w - m4.w) * r4.w * g + be);
        *(float4*)(y + off + (size_t)c * TSZ) = nv;
        if (ADDPOS) {
            float4 pv = *(const float4*)(pos + off + (size_t)c * TSZ);
            float4 ov;
            ov.x = tfr(nv.x + pv.x); ov.y = tfr(nv.y + pv.y);
            ov.z = tfr(nv.z + pv.z); ov.w = tfr(nv.w + pv.w);
            *(float4*)(y2 + off + (size_t)c * TSZ) = ov;
        }
    }
}

// ---------------- elementwise add (tf32-rounded out) -------------------------
__global__ void add4_kernel(const float* __restrict__ a,
                            const float* __restrict__ b,
                            float* __restrict__ o, int n4)
{
    int i = blockIdx.x * blockDim.x + threadIdx.x;
    if (i < n4) {
        float4 av = ((const float4*)a)[i];
        float4 bv = ((const float4*)b)[i];
        float4 ov;
        ov.x = tfr(av.x + bv.x); ov.y = tfr(av.y + bv.y);
        ov.z = tfr(av.z + bv.z); ov.w = tfr(av.w + bv.w);
        ((float4*)o)[i] = ov;
    }
}

// ---------------- cp.async TF32 GEMM, tile 64x128x16, 3-stage, 3 CTAs/SM -----
// Single barrier per iter: the top barrier of iter it+1 orders compute(it)
// before prefetch(it+3 = it mod 3), so the trailing barrier is redundant.
// MODE bit0:+bias  bit1:relu  bit2:+=residual(Y)  bit3:tf32-round out
//      bit4:+residual from separate pointer Rb
#define GSTAGES 3
#define A_STG (64*16)
#define B_STG (16*136)
#define GEMM_SMEM ((GSTAGES*(A_STG+B_STG))*4)

__device__ __forceinline__ void cpa16(uint32_t s, const float* g) {
    asm volatile("cp.async.cg.shared.global [%0], [%1], 16;\n" :: "r"(s), "l"(g));
}

template<int MODE>
__device__ __forceinline__ void gemm_core(const float* __restrict__ Wb,
                                          const float* __restrict__ bias, int biasRow,
                                          const float* __restrict__ Xb,
                                          float* __restrict__ Yb,
                                          const float* __restrict__ Rb, int K)
{
    extern __shared__ float sm_[];
    float* As = sm_;
    float* Bs = sm_ + GSTAGES*A_STG;

    const int tid  = threadIdx.x;
    const int lane = tid & 31;
    const int gid  = lane >> 2;
    const int tig  = lane & 3;
    const int warp = tid >> 5;
    const int wm = (warp & 1) * 32;
    const int wn = (warp >> 1) * 32;

    const int arow = tid >> 2, akc = (tid & 3) * 4;
    const int bkr  = tid >> 4, bnc = (tid & 15) * 8;

    const uint32_t asb = (uint32_t)__cvta_generic_to_shared(As + arow*16 + akc);
    const uint32_t bsb = (uint32_t)__cvta_generic_to_shared(Bs + bkr*136 + bnc);
    const float* ag0 = Wb + (size_t)arow * K + akc;
    const float* bg0 = Xb + (size_t)bkr * TSZ + bnc;

    float acc[2][4][4];
    #pragma unroll
    for (int mi = 0; mi < 2; mi++)
        #pragma unroll
        for (int nj = 0; nj < 4; nj++)
            #pragma unroll
            for (int r = 0; r < 4; r++) acc[mi][nj][r] = 0.f;

    const int nIter = K / 16;

    #pragma unroll
    for (int s = 0; s < GSTAGES - 1; s++) {
        cpa16(asb + s*A_STG*4, ag0 + s*16);
        cpa16(bsb + s*B_STG*4,      bg0 + (size_t)s*16*TSZ);
        cpa16(bsb + s*B_STG*4 + 16, bg0 + (size_t)s*16*TSZ + 4);
        asm volatile("cp.async.commit_group;" ::: "memory");
    }

    for (int it = 0; it < nIter; ++it) {
        asm volatile("cp.async.wait_group 1;" ::: "memory");
        __syncthreads();

        if (it + GSTAGES - 1 < nIter) {
            const int s  = (it + GSTAGES - 1) % GSTAGES;
            const int k0 = (it + GSTAGES - 1) * 16;
            cpa16(asb + s*A_STG*4, ag0 + k0);
            cpa16(bsb + s*B_STG*4,      bg0 + (size_t)k0*TSZ);
            cpa16(bsb + s*B_STG*4 + 16, bg0 + (size_t)k0*TSZ + 4);
        }
        asm volatile("cp.async.commit_group;" ::: "memory");

        const float* Ab = As + (it % GSTAGES) * A_STG;
        const float* Bb = Bs + (it % GSTAGES) * B_STG;

        float4 af[4];
        #pragma unroll
        for (int j = 0; j < 4; j++)
            af[j] = *(const float4*)(Ab + (wm + j*8 + gid)*16 + tig*4);

        #pragma unroll
        for (int kk = 0; kk < 2; kk++) {
            uint32_t b[4][2];
            #pragma unroll
            for (int nj = 0; nj < 4; nj++) {
                const int c = wn + nj * 8 + gid;
                b[nj][0] = __float_as_uint(Bb[(kk*8 + tig)*136 + c]);
                b[nj][1] = __float_as_uint(Bb[(kk*8 + tig + 4)*136 + c]);
            }
            #pragma unroll
            for (int mi = 0; mi < 2; mi++) {
                uint32_t a0, a1, a2, a3;
                if (kk == 0) {
                    a0 = __float_as_uint(af[2*mi].x);   a1 = __float_as_uint(af[2*mi+1].x);
                    a2 = __float_as_uint(af[2*mi].y);   a3 = __float_as_uint(af[2*mi+1].y);
                } else {
                    a0 = __float_as_uint(af[2*mi].z);   a1 = __float_as_uint(af[2*mi+1].z);
                    a2 = __float_as_uint(af[2*mi].w);   a3 = __float_as_uint(af[2*mi+1].w);
                }
                #pragma unroll
                for (int nj = 0; nj < 4; nj++) {
                    asm volatile(
                        "mma.sync.aligned.m16n8k8.row.col.f32.tf32.tf32.f32 "
                        "{%0,%1,%2,%3}, {%4,%5,%6,%7}, {%8,%9}, {%0,%1,%2,%3};"
                        : "+f"(acc[mi][nj][0]), "+f"(acc[mi][nj][1]),
                          "+f"(acc[mi][nj][2]), "+f"(acc[mi][nj][3])
                        : "r"(a0), "r"(a1), "r"(a2), "r"(a3),
                          "r"(b[nj][0]), "r"(b[nj][1]));
                }
            }
        }
        // no trailing barrier: next iter's top barrier orders compute(it)
        // before the prefetch that overwrites this buffer (distance 3).
    }

    #pragma unroll
    for (int mi = 0; mi < 2; mi++) {
        const int r0 = wm + mi * 16 + gid;
        float bia0 = 0.f, bia1 = 0.f;
        if (MODE & 1) {
            bia0 = __ldg(&bias[biasRow + r0]);
            bia1 = __ldg(&bias[biasRow + r0 + 8]);
        }
        #pragma unroll
        for (int nj = 0; nj < 4; nj++) {
            const int c = wn + nj * 8 + tig * 2;
            float2 v0 = make_float2(acc[mi][nj][0] + bia0, acc[mi][nj][1] + bia0);
            float2 v1 = make_float2(acc[mi][nj][2] + bia1, acc[mi][nj][3] + bia1);
            if (MODE & 2) {
                v0.x = fmaxf(v0.x, 0.f); v0.y = fmaxf(v0.y, 0.f);
                v1.x = fmaxf(v1.x, 0.f); v1.y = fmaxf(v1.y, 0.f);
            }
            if (MODE & 8) {
                v0.x = tfr(v0.x); v0.y = tfr(v0.y);
                v1.x = tfr(v1.x); v1.y = tfr(v1.y);
            }
            float* p0 = Yb + (size_t)r0 * TSZ + c;
            float* p1 = Yb + (size_t)(r0 + 8) * TSZ + c;
            if (MODE & 4) {
                float2 o0 = *(const float2*)p0;
                float2 o1 = *(const float2*)p1;
                v0.x += o0.x; v0.y += o0.y;
                v1.x += o1.x; v1.y += o1.y;
            }
            if (MODE & 16) {
                const float* q0 = Rb + (size_t)r0 * TSZ + c;
                const float* q1 = Rb + (size_t)(r0 + 8) * TSZ + c;
                float2 o0 = *(const float2*)q0;
                float2 o1 = *(const float2*)q1;
                v0.x += o0.x; v0.y += o0.y;
                v1.x += o1.x; v1.y += o1.y;
            }
            *(float2*)p0 = v0;
            *(float2*)p1 = v1;
        }
    }
}

template<int MODE>
__global__ __launch_bounds__(256, 3)
void gemm_ca(const float* __restrict__ W, const float* __restrict__ bias,
             const float* __restrict__ X, float* __restrict__ Y,
             const float* __restrict__ R, int M, int K)
{
    const int bx = blockIdx.x, by = blockIdx.y, bz = blockIdx.z;
    size_t off = (size_t)bz * M * TSZ + (size_t)by * 64 * TSZ + bx * 128;
    gemm_core<MODE>(W + (size_t)by * 64 * K, bias, by * 64,
                    X + (size_t)bz * K * TSZ + bx * 128,
                    Y + off, (MODE & 16) ? (R + off) : (const float*)nullptr, K);
}

__global__ __launch_bounds__(256, 3)
void gemm_qkv(const float* __restrict__ Wq, const float* __restrict__ Wk,
              const float* __restrict__ Wv,
              const float* __restrict__ bq, const float* __restrict__ bk,
              const float* __restrict__ bv,
              const float* __restrict__ Xqk, const float* __restrict__ Xv,
              float* __restrict__ Yq, float* __restrict__ Yk, float* __restrict__ Yv)
{
    const int bx = blockIdx.x, by = blockIdx.y, bz = blockIdx.z;
    const int seg = by >> 2, tile = by & 3;
    const float* W  = (seg == 0) ? Wq : (seg == 1) ? Wk : Wv;
    const float* bi = (seg == 0) ? bq : (seg == 1) ? bk : bv;
    const float* X  = (seg < 2) ? Xqk : Xv;
    float*       Y  = (seg == 0) ? Yq : (seg == 1) ? Yk : Yv;
    gemm_core<1>(W + (size_t)tile * 64 * CC, bi, tile * 64,
                 X + (size_t)bz * CC * TSZ + bx * 128,
                 Y + (size_t)bz * CC * TSZ + (size_t)tile * 64 * TSZ + bx * 128,
                 nullptr, CC);
}

// ---------------- sparse attention: single-pass online with zero anchor ------
#define KPAD 36
#define ATTN_SMEM_BYTES ((SSQ*KPAD*2 + 16*33 + 32)*4)

__global__ __launch_bounds__(512, 1)
void attn_sparse(const float* __restrict__ Q, const float* __restrict__ Kg,
                 const float* __restrict__ V, float* __restrict__ out)
{
    extern __shared__ float sm[];
    float* Ks = sm;
    float* Vs = Ks + SSQ*KPAD;
    float* partial = Vs + SSQ*KPAD;
    float* Vsum    = partial + 16*33;
    __shared__ unsigned mw[16];

    int blk = blockIdx.x;
    int b = blk / (HH*TT);
    int rem = blk - b*(HH*TT);
    int h = rem / TT;
    int t = rem - h*TT;
    int bt = b*TT + t;
    int tid = threadIdx.x;
    size_t base = ((size_t)(b*CC + h*HDIM))*TSZ + (size_t)t*SSQ;

    #pragma unroll
    for (int d = 0; d < HDIM; d++) {
        Ks[tid*KPAD + d] = Kg[base + (size_t)d*TSZ + tid];
        Vs[tid*KPAD + d] = V [base + (size_t)d*TSZ + tid];
    }
    if (tid < 16) mw[tid] = g_maskw[bt*16 + tid];
    __syncthreads();

    {
        int d = tid & 31, c = tid >> 5;
        unsigned mk = mw[c];
        float s = 0.f;
        #pragma unroll 8
        for (int jj = 0; jj < 32; jj++)
            if (!((mk >> jj) & 1u)) s += Vs[(c*32 + jj)*KPAD + d];
        partial[c*33 + d] = s;
    }
    __syncthreads();
    if (tid < 32) {
        float s = 0.f;
        #pragma unroll
        for (int c = 0; c < 16; c++) s += partial[c*33 + tid];
        Vsum[tid] = s;
    }
    int N_u = g_nu[bt];
    __syncthreads();

    float qv[HDIM];
    #pragma unroll
    for (int d = 0; d < HDIM; d++) qv[d] = Q[base + (size_t)d*TSZ + tid];

    const float SCL = 0.17677669529663687f;

    float m  = 0.f;
    float p0 = 1.f;
    float l  = (float)N_u;
    float acc[HDIM];
    #pragma unroll
    for (int d = 0; d < HDIM; d++) acc[d] = Vsum[d];

    const unsigned* bptr = g_bits + (size_t)bt*16*SSQ + tid;
    for (int w = 0; w < 16; w++) {
        unsigned bz = __ldg(bptr + w*SSQ);
        while (bz) {
            int j = w*32 + (__ffs(bz) - 1);
            bz &= bz - 1;
            const float4* k4 = (const float4*)(Ks + j*KPAD);
            float dot = 0.f;
            #pragma unroll
            for (int r = 0; r < 8; r++) {
                float4 kk = k4[r];
                dot += qv[4*r]*kk.x + qv[4*r+1]*kk.y + qv[4*r+2]*kk.z + qv[4*r+3]*kk.w;
            }
            float lg = dot * SCL;
            if (lg > m) {
                float sc = __expf(m - lg);
                l *= sc;
                #pragma unroll
                for (int d = 0; d < HDIM; d++) acc[d] *= sc;
                m = lg;
                p0 = __expf(-m);
            }
            float p = __expf(lg - m) - p0;
            l += p;
            const float4* v4 = (const float4*)(Vs + j*KPAD);
            #pragma unroll
            for (int r = 0; r < 8; r++) {
                float4 vv = v4[r];
                acc[4*r]   += p * vv.x;
                acc[4*r+1] += p * vv.y;
                acc[4*r+2] += p * vv.z;
                acc[4*r+3] += p * vv.w;
            }
        }
    }

    float inv = 1.f / l;
    #pragma unroll
    for (int d = 0; d < HDIM; d++)
        out[base + (size_t)d*TSZ + tid] = tfr(acc[d] * inv);
}

// ---------------- orchestration ---------------------------------------------
extern "C" void kernel_launch(void* const* d_in, const int* in_sizes, int n_in,
                              void* d_out, int out_size)
{
    const float* decoder = (const float*)d_in[0];
    const float* encoder = (const float*)d_in[1];
    const float* pos     = (const float*)d_in[2];
    const float* coord   = (const float*)d_in[3];
    const unsigned int* mask = (const unsigned int*)d_in[4];
    const float* Wq = (const float*)d_in[5];
    const float* bq = (const float*)d_in[6];
    const float* Wk = (const float*)d_in[7];
    const float* bk = (const float*)d_in[8];
    const float* Wv = (const float*)d_in[9];
    const float* bv = (const float*)d_in[10];
    const float* Wo = (const float*)d_in[11];
    const float* bo = (const float*)d_in[12];
    const float* W1 = (const float*)d_in[13];
    const float* b1 = (const float*)d_in[14];
    const float* W2 = (const float*)d_in[15];
    const float* b2 = (const float*)d_in[16];
    const float* lng = (const float*)d_in[17];
    const float* lnb = (const float*)d_in[18];
    float* out = (float*)d_out;

    float *src2, *qk, *qkenc, *qb, *kb, *vb, *vals, *hbuf;
    float *rWq, *rWk, *rWv, *rWo, *rW1, *rW2;
    cudaGetSymbolAddress((void**)&src2,  g_src2);
    cudaGetSymbolAddress((void**)&qk,    g_qk);
    cudaGetSymbolAddress((void**)&qkenc, g_qkenc);
    cudaGetSymbolAddress((void**)&qb,    g_qb);
    cudaGetSymbolAddress((void**)&kb,    g_kb);
    cudaGetSymbolAddress((void**)&vb,    g_vb);
    cudaGetSymbolAddress((void**)&vals,  g_vals);
    cudaGetSymbolAddress((void**)&hbuf,  g_h);
    cudaGetSymbolAddress((void**)&rWq,   g_rWq);
    cudaGetSymbolAddress((void**)&rWk,   g_rWk);
    cudaGetSymbolAddress((void**)&rWv,   g_rWv);
    cudaGetSymbolAddress((void**)&rWo,   g_rWo);
    cudaGetSymbolAddress((void**)&rW1,   g_rW1);
    cudaGetSymbolAddress((void**)&rW2,   g_rW2);

    cudaFuncSetAttribute((const void*)attn_sparse,
                         cudaFuncAttributeMaxDynamicSharedMemorySize, ATTN_SMEM_BYTES);
    cudaFuncSetAttribute((const void*)gemm_qkv,
                         cudaFuncAttributeMaxDynamicSharedMemorySize, GEMM_SMEM);
    cudaFuncSetAttribute((const void*)gemm_ca<5>,
                         cudaFuncAttributeMaxDynamicSharedMemorySize, GEMM_SMEM);
    cudaFuncSetAttribute((const void*)gemm_ca<11>,
                         cudaFuncAttributeMaxDynamicSharedMemorySize, GEMM_SMEM);
    cudaFuncSetAttribute((const void*)gemm_ca<17>,
                         cudaFuncAttributeMaxDynamicSharedMemorySize, GEMM_SMEM);

    gate_kernel<<<dim3(BB*TT, 4), 512>>>(coord, mask);
    prep_weights<<<(NGRP_TOT + 127)/128, 128>>>(Wq, Wk, Wv, Wo, W1, W2,
                                                rWq, rWk, rWv, rWo, rW1, rW2);
    add4_kernel<<<(ACTN/4 + 255)/256, 256>>>(encoder, pos, qkenc, ACTN/4);

    dim3 gqkv(TSZ/128, 12, BB);
    dim3 gp(TSZ/128, CC/64, BB);
    dim3 gf(TSZ/128, DFFN/64, BB);
    dim3 lnGrid(NPOS/64);
    int  attnBlocks = BB * HH * TT;

    for (int i = 0; i < 2; i++) {
        const float* rWq_l = rWq + (size_t)i*CC*CC;   const float* bq_l = bq + (size_t)i*CC;
        const float* rWk_l = rWk + (size_t)i*CC*CC;   const float* bk_l = bk + (size_t)i*CC;
        const float* rWv_l = rWv + (size_t)i*CC*CC;   const float* bv_l = bv + (size_t)i*CC;
        const float* rWo_l = rWo + (size_t)i*CC*CC;   const float* bo_l = bo + (size_t)i*CC;
        const float* rW1_l = rW1 + (size_t)i*DFFN*CC; const float* b1_l = b1 + (size_t)i*DFFN;
        const float* rW2_l = rW2 + (size_t)i*CC*DFFN; const float* b2_l = b2 + (size_t)i*CC;
        const float* g0 = lng + (size_t)(i*3+0)*CC; const float* be0 = lnb + (size_t)(i*3+0)*CC;
        const float* g1 = lng + (size_t)(i*3+1)*CC; const float* be1 = lnb + (size_t)(i*3+1)*CC;
        const float* g2 = lng + (size_t)(i*3+2)*CC; const float* be2 = lnb + (size_t)(i*3+2)*CC;

        // ---- block 1: q/k = LN(dec)+pos (fused), v = LN(dec) ----
        const float* resid_in = (i == 0) ? decoder : out;
        ln_fast<true><<<lnGrid, 256>>>(resid_in, g0, be0, src2, pos, qk);
        gemm_qkv<<<gqkv, 256, GEMM_SMEM>>>(rWq_l, rWk_l, rWv_l, bq_l, bk_l, bv_l,
                                           qk, src2, qb, kb, vb);
        attn_sparse<<<attnBlocks, 512, ATTN_SMEM_BYTES>>>(qb, kb, vb, vals);
        if (i == 0)
            gemm_ca<17><<<gp, 256, GEMM_SMEM>>>(rWo_l, bo_l, vals, out, decoder, CC, CC);
        else
            gemm_ca<5><<<gp, 256, GEMM_SMEM>>>(rWo_l, bo_l, vals, out, nullptr, CC, CC);

        // ---- block 2: q/k = encoder+pos, v = LN(dec) ----
        ln_fast<false><<<lnGrid, 256>>>(out, g1, be1, src2, nullptr, nullptr);
        gemm_qkv<<<gqkv, 256, GEMM_SMEM>>>(rWq_l, rWk_l, rWv_l, bq_l, bk_l, bv_l,
                                           qkenc, src2, qb, kb, vb);
        attn_sparse<<<attnBlocks, 512, ATTN_SMEM_BYTES>>>(qb, kb, vb, vals);
        gemm_ca<5><<<gp, 256, GEMM_SMEM>>>(rWo_l, bo_l, vals, out, nullptr, CC, CC);

        // ---- FFN ----
        ln_fast<false><<<lnGrid, 256>>>(out, g2, be2, src2, nullptr, nullptr);
        gemm_ca<11><<<gf, 256, GEMM_SMEM>>>(rW1_l, b1_l, src2, hbuf, nullptr, DFFN, CC);
        gemm_ca<5><<<gp, 256, GEMM_SMEM>>>(rW2_l, b2_l, hbuf, out, nullptr, CC, DFFN);
    }
}

// round 13
// speedup vs baseline: 1.5213x; 1.5213x over previous
#include <cuda_runtime.h>
#include <cstdint>
#include <math.h>

// ---------------- problem constants ----------------
#define BB   2
#define CC   256
#define HH   8
#define HDIM 32
#define TT   16
#define SSQ  512
#define DFFN 1024
#define TSZ  (TT*SSQ)          // 8192
#define ACTN (BB*CC*TSZ)       // 4,194,304 floats
#define NPOS (BB*TSZ)          // 16384 positions

// ---------------- scratch ----------------------------------------------------
__device__ float g_src2[ACTN];
__device__ float g_qk[ACTN];
__device__ float g_qkenc[ACTN];
__device__ float g_qb[ACTN];
__device__ float g_kb[ACTN];
__device__ float g_vb[ACTN];
__device__ float g_vals[ACTN];
__device__ float g_h[BB*DFFN*TSZ];

// pre-rounded + k-permuted weights
__device__ float g_rWq[2*CC*CC];
__device__ float g_rWk[2*CC*CC];
__device__ float g_rWv[2*CC*CC];
__device__ float g_rWo[2*CC*CC];
__device__ float g_rW1[2*DFFN*CC];
__device__ float g_rW2[2*CC*DFFN];

// sparse-attention precompute
__device__ unsigned g_bits[BB*TT*16*SSQ];
__device__ unsigned g_maskw[BB*TT*16];
__device__ int      g_nu[BB*TT];

__device__ __forceinline__ uint32_t f2tf(float x) {
    uint32_t u;
    asm("cvt.rna.tf32.f32 %0, %1;" : "=r"(u) : "f"(x));
    return u;
}
__device__ __forceinline__ float tfr(float x) { return __uint_as_float(f2tf(x)); }

// ---------------- weight prep: tf32-round + within-16-group k-permute --------
#define NGRP_PROJ (2*CC*CC/16)
#define NGRP_FFN  (2*DFFN*CC/16)
#define NGRP_TOT  (4*NGRP_PROJ + 2*NGRP_FFN)

__global__ void prep_weights(const float* __restrict__ Wq, const float* __restrict__ Wk,
                             const float* __restrict__ Wv, const float* __restrict__ Wo,
                             const float* __restrict__ W1, const float* __restrict__ W2,
                             float* __restrict__ rWq, float* __restrict__ rWk,
                             float* __restrict__ rWv, float* __restrict__ rWo,
                             float* __restrict__ rW1, float* __restrict__ rW2)
{
    int g = blockIdx.x * blockDim.x + threadIdx.x;
    if (g >= NGRP_TOT) return;
    const float* src; float* dst; int lg = g;
    if      (g <  NGRP_PROJ)            { src = Wq; dst = rWq; }
    else if (g < 2*NGRP_PROJ)           { src = Wk; dst = rWk; lg = g - NGRP_PROJ; }
    else if (g < 3*NGRP_PROJ)           { src = Wv; dst = rWv; lg = g - 2*NGRP_PROJ; }
    else if (g < 4*NGRP_PROJ)           { src = Wo; dst = rWo; lg = g - 3*NGRP_PROJ; }
    else if (g < 4*NGRP_PROJ+NGRP_FFN)  { src = W1; dst = rW1; lg = g - 4*NGRP_PROJ; }
    else                                { src = W2; dst = rW2; lg = g - 4*NGRP_PROJ - NGRP_FFN; }
    size_t base = (size_t)lg * 16;
    float v[16];
    #pragma unroll
    for (int j = 0; j < 16; j++) v[j] = src[base + j];
    #pragma unroll
    for (int p = 0; p < 16; p++) dst[base + p] = tfr(v[(p & 3) * 4 + (p >> 2)]);
}

// ---------------- gate/mask bit precompute -----------------------------------
__global__ void gate_kernel(const float* __restrict__ coord,
                            const unsigned* __restrict__ mask)
{
    __shared__ float cs[SSQ*3];
    __shared__ unsigned mw[16];
    int bt  = blockIdx.x;
    int wg  = blockIdx.y;
    int tid = threadIdx.x;

    size_t cbase = (size_t)bt * SSQ * 3;
    for (int i = tid; i < SSQ*3; i += 512) cs[i] = coord[cbase + i];
    unsigned mv  = (mask[(size_t)bt*SSQ + tid] != 0u);
    unsigned bal = __ballot_sync(0xffffffffu, mv);
    if ((tid & 31) == 0) mw[tid >> 5] = bal;
    __syncthreads();

    if (wg == 0) {
        if (tid == 0) {
            int nm = 0;
            for (int w = 0; w < 16; w++) nm += __popc(mw[w]);
            g_nu[bt] = SSQ - nm;
        }
        if (tid < 16) g_maskw[bt*16 + tid] = mw[tid];
    }

    float qx = cs[tid*3], qy = cs[tid*3+1], qz = cs[tid*3+2];
    for (int w = wg*4; w < wg*4 + 4; w++) {
        unsigned bits = 0, mk = mw[w];
        #pragma unroll
        for (int bb = 0; bb < 32; bb++) {
            int j = w*32 + bb;
            float dx = qx - cs[j*3], dy = qy - cs[j*3+1], dz = qz - cs[j*3+2];
            float d2 = dx*dx + dy*dy + dz*dz;
            if (d2 < 625.0f && !((mk >> bb) & 1u)) bits |= (1u << bb);
        }
        g_bits[((size_t)bt*16 + w)*SSQ + tid] = bits;
    }
}

// ---------------- fast LayerNorm: 512 thr/CTA, 8 channels/thread -------------
// thread (c8=tid>>4, pg=tid&15): channels c8*8..+7, positions pg*4..+3 (float4)
template<bool ADDPOS>
__global__ __launch_bounds__(512)
void ln_fast(const float* __restrict__ x,
             const float* __restrict__ gamma,
             const float* __restrict__ beta,
             float* __restrict__ y,
             const float* __restrict__ pos,
             float* __restrict__ y2)
{
    __shared__ float red_s[32][64];
    __shared__ float red_q[32][64];
    __shared__ float mu[64], rs[64];

    const int tid = threadIdx.x;
    const int c8  = tid >> 4;          // channel chunk 0..31 (8 channels each)
    const int pg  = tid & 15;          // position group 0..15
    const int p0  = blockIdx.x * 64 + pg * 4;
    const int b   = p0 / TSZ;          // 64-pos blocks never straddle batches
    const int pi  = p0 - b * TSZ;
    const float* xb = x + (size_t)b * CC * TSZ + pi;

    float4 v[8];
    float4 s = make_float4(0.f,0.f,0.f,0.f), q = make_float4(0.f,0.f,0.f,0.f);
    #pragma unroll
    for (int i = 0; i < 8; i++) {
        v[i] = *(const float4*)(xb + (size_t)(c8*8 + i) * TSZ);
        s.x += v[i].x; s.y += v[i].y; s.z += v[i].z; s.w += v[i].w;
        q.x += v[i].x*v[i].x; q.y += v[i].y*v[i].y;
        q.z += v[i].z*v[i].z; q.w += v[i].w*v[i].w;
    }
    red_s[c8][pg*4+0] = s.x; red_s[c8][pg*4+1] = s.y;
    red_s[c8][pg*4+2] = s.z; red_s[c8][pg*4+3] = s.w;
    red_q[c8][pg*4+0] = q.x; red_q[c8][pg*4+1] = q.y;
    red_q[c8][pg*4+2] = q.z; red_q[c8][pg*4+3] = q.w;
    __syncthreads();

    if (tid < 64) {
        float ts = 0.f, tq = 0.f;
        #pragma unroll
        for (int k = 0; k < 32; k++) { ts += red_s[k][tid]; tq += red_q[k][tid]; }
        float m   = ts * (1.0f/CC);
        float var = tq * (1.0f/CC) - m*m;
        mu[tid] = m;
        rs[tid] = rsqrtf(var + 1e-5f);
    }
    __syncthreads();

    float4 m4 = *(const float4*)(mu + pg*4);
    float4 r4 = *(const float4*)(rs + pg*4);
    size_t off = (size_t)b * CC * TSZ + pi;

    #pragma unroll
    for (int i = 0; i < 8; i++) {
        const int c = c8*8 + i;
        const float g = __ldg(&gamma[c]), be = __ldg(&beta[c]);
        float4 nv;
        nv.x = tfr((v[i].x - m4.x) * r4.x * g + be);
        nv.y = tfr((v[i].y - m4.y) * r4.y * g + be);
        nv.z = tfr((v[i].z - m4.z) * r4.z * g + be);
        nv.w = tfr((v[i].w - m4.w) * r4.w * g + be);
        *(float4*)(y + off + (size_t)c * TSZ) = nv;
        if (ADDPOS) {
            float4 pv = *(const float4*)(pos + off + (size_t)c * TSZ);
            float4 ov;
            ov.x = tfr(nv.x + pv.x); ov.y = tfr(nv.y + pv.y);
            ov.z = tfr(nv.z + pv.z); ov.w = tfr(nv.w + pv.w);
            *(float4*)(y2 + off + (size_t)c * TSZ) = ov;
        }
    }
}

// ---------------- elementwise add (tf32-rounded out) -------------------------
__global__ void add4_kernel(const float* __restrict__ a,
                            const float* __restrict__ b,
                            float* __restrict__ o, int n4)
{
    int i = blockIdx.x * blockDim.x + threadIdx.x;
    if (i < n4) {
        float4 av = ((const float4*)a)[i];
        float4 bv = ((const float4*)b)[i];
        float4 ov;
        ov.x = tfr(av.x + bv.x); ov.y = tfr(av.y + bv.y);
        ov.z = tfr(av.z + bv.z); ov.w = tfr(av.w + bv.w);
        ((float4*)o)[i] = ov;
    }
}

// ---------------- cp.async TF32 GEMM, tile 64x128x16, 3-stage, 3 CTAs/SM -----
// (R9 configuration, verbatim: two barriers per iter — empirically fastest.)
// MODE bit0:+bias  bit1:relu  bit2:+=residual(Y)  bit3:tf32-round out
//      bit4:+residual from separate pointer Rb
#define GSTAGES 3
#define A_STG (64*16)
#define B_STG (16*136)
#define GEMM_SMEM ((GSTAGES*(A_STG+B_STG))*4)

__device__ __forceinline__ void cpa16(uint32_t s, const float* g) {
    asm volatile("cp.async.cg.shared.global [%0], [%1], 16;\n" :: "r"(s), "l"(g));
}

template<int MODE>
__device__ __forceinline__ void gemm_core(const float* __restrict__ Wb,
                                          const float* __restrict__ bias, int biasRow,
                                          const float* __restrict__ Xb,
                                          float* __restrict__ Yb,
                                          const float* __restrict__ Rb, int K)
{
    extern __shared__ float sm_[];
    float* As = sm_;
    float* Bs = sm_ + GSTAGES*A_STG;

    const int tid  = threadIdx.x;
    const int lane = tid & 31;
    const int gid  = lane >> 2;
    const int tig  = lane & 3;
    const int warp = tid >> 5;
    const int wm = (warp & 1) * 32;
    const int wn = (warp >> 1) * 32;

    const int arow = tid >> 2, akc = (tid & 3) * 4;
    const int bkr  = tid >> 4, bnc = (tid & 15) * 8;

    const uint32_t asb = (uint32_t)__cvta_generic_to_shared(As + arow*16 + akc);
    const uint32_t bsb = (uint32_t)__cvta_generic_to_shared(Bs + bkr*136 + bnc);
    const float* ag0 = Wb + (size_t)arow * K + akc;
    const float* bg0 = Xb + (size_t)bkr * TSZ + bnc;

    float acc[2][4][4];
    #pragma unroll
    for (int mi = 0; mi < 2; mi++)
        #pragma unroll
        for (int nj = 0; nj < 4; nj++)
            #pragma unroll
            for (int r = 0; r < 4; r++) acc[mi][nj][r] = 0.f;

    const int nIter = K / 16;

    #pragma unroll
    for (int s = 0; s < GSTAGES - 1; s++) {
        cpa16(asb + s*A_STG*4, ag0 + s*16);
        cpa16(bsb + s*B_STG*4,      bg0 + (size_t)s*16*TSZ);
        cpa16(bsb + s*B_STG*4 + 16, bg0 + (size_t)s*16*TSZ + 4);
        asm volatile("cp.async.commit_group;" ::: "memory");
    }

    for (int it = 0; it < nIter; ++it) {
        asm volatile("cp.async.wait_group 1;" ::: "memory");
        __syncthreads();

        if (it + GSTAGES - 1 < nIter) {
            const int s  = (it + GSTAGES - 1) % GSTAGES;
            const int k0 = (it + GSTAGES - 1) * 16;
            cpa16(asb + s*A_STG*4, ag0 + k0);
            cpa16(bsb + s*B_STG*4,      bg0 + (size_t)k0*TSZ);
            cpa16(bsb + s*B_STG*4 + 16, bg0 + (size_t)k0*TSZ + 4);
        }
        asm volatile("cp.async.commit_group;" ::: "memory");

        const float* Ab = As + (it % GSTAGES) * A_STG;
        const float* Bb = Bs + (it % GSTAGES) * B_STG;

        float4 af[4];
        #pragma unroll
        for (int j = 0; j < 4; j++)
            af[j] = *(const float4*)(Ab + (wm + j*8 + gid)*16 + tig*4);

        #pragma unroll
        for (int kk = 0; kk < 2; kk++) {
            uint32_t b[4][2];
            #pragma unroll
            for (int nj = 0; nj < 4; nj++) {
                const int c = wn + nj * 8 + gid;
                b[nj][0] = __float_as_uint(Bb[(kk*8 + tig)*136 + c]);
                b[nj][1] = __float_as_uint(Bb[(kk*8 + tig + 4)*136 + c]);
            }
            #pragma unroll
            for (int mi = 0; mi < 2; mi++) {
                uint32_t a0, a1, a2, a3;
                if (kk == 0) {
                    a0 = __float_as_uint(af[2*mi].x);   a1 = __float_as_uint(af[2*mi+1].x);
                    a2 = __float_as_uint(af[2*mi].y);   a3 = __float_as_uint(af[2*mi+1].y);
                } else {
                    a0 = __float_as_uint(af[2*mi].z);   a1 = __float_as_uint(af[2*mi+1].z);
                    a2 = __float_as_uint(af[2*mi].w);   a3 = __float_as_uint(af[2*mi+1].w);
                }
                #pragma unroll
                for (int nj = 0; nj < 4; nj++) {
                    asm volatile(
                        "mma.sync.aligned.m16n8k8.row.col.f32.tf32.tf32.f32 "
                        "{%0,%1,%2,%3}, {%4,%5,%6,%7}, {%8,%9}, {%0,%1,%2,%3};"
                        : "+f"(acc[mi][nj][0]), "+f"(acc[mi][nj][1]),
                          "+f"(acc[mi][nj][2]), "+f"(acc[mi][nj][3])
                        : "r"(a0), "r"(a1), "r"(a2), "r"(a3),
                          "r"(b[nj][0]), "r"(b[nj][1]));
                }
            }
        }
        __syncthreads();
    }

    #pragma unroll
    for (int mi = 0; mi < 2; mi++) {
        const int r0 = wm + mi * 16 + gid;
        float bia0 = 0.f, bia1 = 0.f;
        if (MODE & 1) {
            bia0 = __ldg(&bias[biasRow + r0]);
            bia1 = __ldg(&bias[biasRow + r0 + 8]);
        }
        #pragma unroll
        for (int nj = 0; nj < 4; nj++) {
            const int c = wn + nj * 8 + tig * 2;
            float2 v0 = make_float2(acc[mi][nj][0] + bia0, acc[mi][nj][1] + bia0);
            float2 v1 = make_float2(acc[mi][nj][2] + bia1, acc[mi][nj][3] + bia1);
            if (MODE & 2) {
                v0.x = fmaxf(v0.x, 0.f); v0.y = fmaxf(v0.y, 0.f);
                v1.x = fmaxf(v1.x, 0.f); v1.y = fmaxf(v1.y, 0.f);
            }
            if (MODE & 8) {
                v0.x = tfr(v0.x); v0.y = tfr(v0.y);
                v1.x = tfr(v1.x); v1.y = tfr(v1.y);
            }
            float* p0 = Yb + (size_t)r0 * TSZ + c;
            float* p1 = Yb + (size_t)(r0 + 8) * TSZ + c;
            if (MODE & 4) {
                float2 o0 = *(const float2*)p0;
                float2 o1 = *(const float2*)p1;
                v0.x += o0.x; v0.y += o0.y;
                v1.x += o1.x; v1.y += o1.y;
            }
            if (MODE & 16) {
                const float* q0 = Rb + (size_t)r0 * TSZ + c;
                const float* q1 = Rb + (size_t)(r0 + 8) * TSZ + c;
                float2 o0 = *(const float2*)q0;
                float2 o1 = *(const float2*)q1;
                v0.x += o0.x; v0.y += o0.y;
                v1.x += o1.x; v1.y += o1.y;
            }
            *(float2*)p0 = v0;
            *(float2*)p1 = v1;
        }
    }
}

template<int MODE>
__global__ __launch_bounds__(256, 3)
void gemm_ca(const float* __restrict__ W, const float* __restrict__ bias,
             const float* __restrict__ X, float* __restrict__ Y,
             const float* __restrict__ R, int M, int K)
{
    const int bx = blockIdx.x, by = blockIdx.y, bz = blockIdx.z;
    size_t off = (size_t)bz * M * TSZ + (size_t)by * 64 * TSZ + bx * 128;
    gemm_core<MODE>(W + (size_t)by * 64 * K, bias, by * 64,
                    X + (size_t)bz * K * TSZ + bx * 128,
                    Y + off, (MODE & 16) ? (R + off) : (const float*)nullptr, K);
}

__global__ __launch_bounds__(256, 3)
void gemm_qkv(const float* __restrict__ Wq, const float* __restrict__ Wk,
              const float* __restrict__ Wv,
              const float* __restrict__ bq, const float* __restrict__ bk,
              const float* __restrict__ bv,
              const float* __restrict__ Xqk, const float* __restrict__ Xv,
              float* __restrict__ Yq, float* __restrict__ Yk, float* __restrict__ Yv)
{
    const int bx = blockIdx.x, by = blockIdx.y, bz = blockIdx.z;
    const int seg = by >> 2, tile = by & 3;
    const float* W  = (seg == 0) ? Wq : (seg == 1) ? Wk : Wv;
    const float* bi = (seg == 0) ? bq : (seg == 1) ? bk : bv;
    const float* X  = (seg < 2) ? Xqk : Xv;
    float*       Y  = (seg == 0) ? Yq : (seg == 1) ? Yk : Yv;
    gemm_core<1>(W + (size_t)tile * 64 * CC, bi, tile * 64,
                 X + (size_t)bz * CC * TSZ + bx * 128,
                 Y + (size_t)bz * CC * TSZ + (size_t)tile * 64 * TSZ + bx * 128,
                 nullptr, CC);
}

// ---------------- sparse attention: single-pass online with zero anchor ------
#define KPAD 36
#define ATTN_SMEM_BYTES ((SSQ*KPAD*2 + 16*33 + 32)*4)

__global__ __launch_bounds__(512, 1)
void attn_sparse(const float* __restrict__ Q, const float* __restrict__ Kg,
                 const float* __restrict__ V, float* __restrict__ out)
{
    extern __shared__ float sm[];
    float* Ks = sm;
    float* Vs = Ks + SSQ*KPAD;
    float* partial = Vs + SSQ*KPAD;
    float* Vsum    = partial + 16*33;
    __shared__ unsigned mw[16];

    int blk = blockIdx.x;
    int b = blk / (HH*TT);
    int rem = blk - b*(HH*TT);
    int h = rem / TT;
    int t = rem - h*TT;
    int bt = b*TT + t;
    int tid = threadIdx.x;
    size_t base = ((size_t)(b*CC + h*HDIM))*TSZ + (size_t)t*SSQ;

    #pragma unroll
    for (int d = 0; d < HDIM; d++) {
        Ks[tid*KPAD + d] = Kg[base + (size_t)d*TSZ + tid];
        Vs[tid*KPAD + d] = V [base + (size_t)d*TSZ + tid];
    }
    if (tid < 16) mw[tid] = g_maskw[bt*16 + tid];
    __syncthreads();

    {
        int d = tid & 31, c = tid >> 5;
        unsigned mk = mw[c];
        float s = 0.f;
        #pragma unroll 8
        for (int jj = 0; jj < 32; jj++)
            if (!((mk >> jj) & 1u)) s += Vs[(c*32 + jj)*KPAD + d];
        partial[c*33 + d] = s;
    }
    __syncthreads();
    if (tid < 32) {
        float s = 0.f;
        #pragma unroll
        for (int c = 0; c < 16; c++) s += partial[c*33 + tid];
        Vsum[tid] = s;
    }
    int N_u = g_nu[bt];
    __syncthreads();

    float qv[HDIM];
    #pragma unroll
    for (int d = 0; d < HDIM; d++) qv[d] = Q[base + (size_t)d*TSZ + tid];

    const float SCL = 0.17677669529663687f;

    float m  = 0.f;
    float p0 = 1.f;
    float l  = (float)N_u;
    float acc[HDIM];
    #pragma unroll
    for (int d = 0; d < HDIM; d++) acc[d] = Vsum[d];

    const unsigned* bptr = g_bits + (size_t)bt*16*SSQ + tid;
    for (int w = 0; w < 16; w++) {
        unsigned bz = __ldg(bptr + w*SSQ);
        while (bz) {
            int j = w*32 + (__ffs(bz) - 1);
            bz &= bz - 1;
            const float4* k4 = (const float4*)(Ks + j*KPAD);
            float dot = 0.f;
            #pragma unroll
            for (int r = 0; r < 8; r++) {
                float4 kk = k4[r];
                dot += qv[4*r]*kk.x + qv[4*r+1]*kk.y + qv[4*r+2]*kk.z + qv[4*r+3]*kk.w;
            }
            float lg = dot * SCL;
            if (lg > m) {
                float sc = __expf(m - lg);
                l *= sc;
                #pragma unroll
                for (int d = 0; d < HDIM; d++) acc[d] *= sc;
                m = lg;
                p0 = __expf(-m);
            }
            float p = __expf(lg - m) - p0;
            l += p;
            const float4* v4 = (const float4*)(Vs + j*KPAD);
            #pragma unroll
            for (int r = 0; r < 8; r++) {
                float4 vv = v4[r];
                acc[4*r]   += p * vv.x;
                acc[4*r+1] += p * vv.y;
                acc[4*r+2] += p * vv.z;
                acc[4*r+3] += p * vv.w;
            }
        }
    }

    float inv = 1.f / l;
    #pragma unroll
    for (int d = 0; d < HDIM; d++)
        out[base + (size_t)d*TSZ + tid] = tfr(acc[d] * inv);
}

// ---------------- orchestration ---------------------------------------------
extern "C" void kernel_launch(void* const* d_in, const int* in_sizes, int n_in,
                              void* d_out, int out_size)
{
    const float* decoder = (const float*)d_in[0];
    const float* encoder = (const float*)d_in[1];
    const float* pos     = (const float*)d_in[2];
    const float* coord   = (const float*)d_in[3];
    const unsigned int* mask = (const unsigned int*)d_in[4];
    const float* Wq = (const float*)d_in[5];
    const float* bq = (const float*)d_in[6];
    const float* Wk = (const float*)d_in[7];
    const float* bk = (const float*)d_in[8];
    const float* Wv = (const float*)d_in[9];
    const float* bv = (const float*)d_in[10];
    const float* Wo = (const float*)d_in[11];
    const float* bo = (const float*)d_in[12];
    const float* W1 = (const float*)d_in[13];
    const float* b1 = (const float*)d_in[14];
    const float* W2 = (const float*)d_in[15];
    const float* b2 = (const float*)d_in[16];
    const float* lng = (const float*)d_in[17];
    const float* lnb = (const float*)d_in[18];
    float* out = (float*)d_out;

    float *src2, *qk, *qkenc, *qb, *kb, *vb, *vals, *hbuf;
    float *rWq, *rWk, *rWv, *rWo, *rW1, *rW2;
    cudaGetSymbolAddress((void**)&src2,  g_src2);
    cudaGetSymbolAddress((void**)&qk,    g_qk);
    cudaGetSymbolAddress((void**)&qkenc, g_qkenc);
    cudaGetSymbolAddress((void**)&qb,    g_qb);
    cudaGetSymbolAddress((void**)&kb,    g_kb);
    cudaGetSymbolAddress((void**)&vb,    g_vb);
    cudaGetSymbolAddress((void**)&vals,  g_vals);
    cudaGetSymbolAddress((void**)&hbuf,  g_h);
    cudaGetSymbolAddress((void**)&rWq,   g_rWq);
    cudaGetSymbolAddress((void**)&rWk,   g_rWk);
    cudaGetSymbolAddress((void**)&rWv,   g_rWv);
    cudaGetSymbolAddress((void**)&rWo,   g_rWo);
    cudaGetSymbolAddress((void**)&rW1,   g_rW1);
    cudaGetSymbolAddress((void**)&rW2,   g_rW2);

    cudaFuncSetAttribute((const void*)attn_sparse,
                         cudaFuncAttributeMaxDynamicSharedMemorySize, ATTN_SMEM_BYTES);
    cudaFuncSetAttribute((const void*)gemm_qkv,
                         cudaFuncAttributeMaxDynamicSharedMemorySize, GEMM_SMEM);
    cudaFuncSetAttribute((const void*)gemm_ca<5>,
                         cudaFuncAttributeMaxDynamicSharedMemorySize, GEMM_SMEM);
    cudaFuncSetAttribute((const void*)gemm_ca<11>,
                         cudaFuncAttributeMaxDynamicSharedMemorySize, GEMM_SMEM);
    cudaFuncSetAttribute((const void*)gemm_ca<17>,
                         cudaFuncAttributeMaxDynamicSharedMemorySize, GEMM_SMEM);

    gate_kernel<<<dim3(BB*TT, 4), 512>>>(coord, mask);
    prep_weights<<<(NGRP_TOT + 127)/128, 128>>>(Wq, Wk, Wv, Wo, W1, W2,
                                                rWq, rWk, rWv, rWo, rW1, rW2);
    add4_kernel<<<(ACTN/4 + 255)/256, 256>>>(encoder, pos, qkenc, ACTN/4);

    dim3 gqkv(TSZ/128, 12, BB);
    dim3 gp(TSZ/128, CC/64, BB);
    dim3 gf(TSZ/128, DFFN/64, BB);
    dim3 lnGrid(NPOS/64);               // 256 CTAs x 512 thr
    int  attnBlocks = BB * HH * TT;

    for (int i = 0; i < 2; i++) {
        const float* rWq_l = rWq + (size_t)i*CC*CC;   const float* bq_l = bq + (size_t)i*CC;
        const float* rWk_l = rWk + (size_t)i*CC*CC;   const float* bk_l = bk + (size_t)i*CC;
        const float* rWv_l = rWv + (size_t)i*CC*CC;   const float* bv_l = bv + (size_t)i*CC;
        const float* rWo_l = rWo + (size_t)i*CC*CC;   const float* bo_l = bo + (size_t)i*CC;
        const float* rW1_l = rW1 + (size_t)i*DFFN*CC; const float* b1_l = b1 + (size_t)i*DFFN;
        const float* rW2_l = rW2 + (size_t)i*CC*DFFN; const float* b2_l = b2 + (size_t)i*CC;
        const float* g0 = lng + (size_t)(i*3+0)*CC; const float* be0 = lnb + (size_t)(i*3+0)*CC;
        const float* g1 = lng + (size_t)(i*3+1)*CC; const float* be1 = lnb + (size_t)(i*3+1)*CC;
        const float* g2 = lng + (size_t)(i*3+2)*CC; const float* be2 = lnb + (size_t)(i*3+2)*CC;

        // ---- block 1: q/k = LN(dec)+pos (fused), v = LN(dec) ----
        const float* resid_in = (i == 0) ? decoder : out;
        ln_fast<true><<<lnGrid, 512>>>(resid_in, g0, be0, src2, pos, qk);
        gemm_qkv<<<gqkv, 256, GEMM_SMEM>>>(rWq_l, rWk_l, rWv_l, bq_l, bk_l, bv_l,
                                           qk, src2, qb, kb, vb);
        attn_sparse<<<attnBlocks, 512, ATTN_SMEM_BYTES>>>(qb, kb, vb, vals);
        if (i == 0)
            gemm_ca<17><<<gp, 256, GEMM_SMEM>>>(rWo_l, bo_l, vals, out, decoder, CC, CC);
        else
            gemm_ca<5><<<gp, 256, GEMM_SMEM>>>(rWo_l, bo_l, vals, out, nullptr, CC, CC);

        // ---- block 2: q/k = encoder+pos, v = LN(dec) ----
        ln_fast<false><<<lnGrid, 512>>>(out, g1, be1, src2, nullptr, nullptr);
        gemm_qkv<<<gqkv, 256, GEMM_SMEM>>>(rWq_l, rWk_l, rWv_l, bq_l, bk_l, bv_l,
                                           qkenc, src2, qb, kb, vb);
        attn_sparse<<<attnBlocks, 512, ATTN_SMEM_BYTES>>>(qb, kb, vb, vals);
        gemm_ca<5><<<gp, 256, GEMM_SMEM>>>(rWo_l, bo_l, vals, out, nullptr, CC, CC);

        // ---- FFN ----
        ln_fast<false><<<lnGrid, 512>>>(out, g2, be2, src2, nullptr, nullptr);
        gemm_ca<11><<<gf, 256, GEMM_SMEM>>>(rW1_l, b1_l, src2, hbuf, nullptr, DFFN, CC);
        gemm_ca<5><<<gp, 256, GEMM_SMEM>>>(rW2_l, b2_l, hbuf, out, nullptr, CC, DFFN);
    }
}

// round 14
// speedup vs baseline: 1.5503x; 1.0191x over previous
#include <cuda_runtime.h>
#include <cstdint>
#include <math.h>

// ---------------- problem constants ----------------
#define BB   2
#define CC   256
#define HH   8
#define HDIM 32
#define TT   16
#define SSQ  512
#define DFFN 1024
#define TSZ  (TT*SSQ)          // 8192
#define ACTN (BB*CC*TSZ)       // 4,194,304 floats
#define NPOS (BB*TSZ)          // 16384 positions

// ---------------- scratch ----------------------------------------------------
__device__ float g_src2[ACTN];
__device__ float g_qk[ACTN];
__device__ float g_qkenc[ACTN];
__device__ float g_qb[ACTN];
__device__ float g_kb[ACTN];
__device__ float g_vb[ACTN];
__device__ float g_vals[ACTN];
__device__ float g_h[BB*DFFN*TSZ];

// pre-rounded + k-permuted weights
__device__ float g_rWq[2*CC*CC];
__device__ float g_rWk[2*CC*CC];
__device__ float g_rWv[2*CC*CC];
__device__ float g_rWo[2*CC*CC];
__device__ float g_rW1[2*DFFN*CC];
__device__ float g_rW2[2*CC*DFFN];

// sparse-attention precompute
__device__ unsigned g_bits[BB*TT*16*SSQ];
__device__ unsigned g_maskw[BB*TT*16];
__device__ int      g_nu[BB*TT];

__device__ __forceinline__ uint32_t f2tf(float x) {
    uint32_t u;
    asm("cvt.rna.tf32.f32 %0, %1;" : "=r"(u) : "f"(x));
    return u;
}
__device__ __forceinline__ float tfr(float x) { return __uint_as_float(f2tf(x)); }

// ---------------- fused prologue: gate bits + weight prep + (enc+pos) --------
// block ranges: [0,128)            -> gate  (bt = bid>>2, wg = bid&3)
//               [128,128+192)      -> weight round+permute (512 grp/blk)
//               [320, 320+2048)    -> qkenc = tfr(encoder+pos) (512 f4/blk)
#define NGRP_PROJ (2*CC*CC/16)
#define NGRP_FFN  (2*DFFN*CC/16)
#define NGRP_TOT  (4*NGRP_PROJ + 2*NGRP_FFN)      // 98304 = 192*512
#define PRO_GATE   128
#define PRO_PREP   192
#define PRO_ADD    (ACTN/4/512)                   // 2048
#define PRO_BLOCKS (PRO_GATE + PRO_PREP + PRO_ADD)

__global__ __launch_bounds__(512)
void prologue_kernel(const float* __restrict__ coord,
                     const unsigned* __restrict__ mask,
                     const float* __restrict__ Wq, const float* __restrict__ Wk,
                     const float* __restrict__ Wv, const float* __restrict__ Wo,
                     const float* __restrict__ W1, const float* __restrict__ W2,
                     float* __restrict__ rWq, float* __restrict__ rWk,
                     float* __restrict__ rWv, float* __restrict__ rWo,
                     float* __restrict__ rW1, float* __restrict__ rW2,
                     const float* __restrict__ enc, const float* __restrict__ pos,
                     float* __restrict__ qkenc)
{
    const int bid = blockIdx.x;
    const int tid = threadIdx.x;

    if (bid < PRO_GATE) {
        // ---- gate/mask bits ----
        __shared__ float cs[SSQ*3];
        __shared__ unsigned mw[16];
        int bt = bid >> 2;
        int wg = bid & 3;

        size_t cbase = (size_t)bt * SSQ * 3;
        for (int i = tid; i < SSQ*3; i += 512) cs[i] = coord[cbase + i];
        unsigned mv  = (mask[(size_t)bt*SSQ + tid] != 0u);
        unsigned bal = __ballot_sync(0xffffffffu, mv);
        if ((tid & 31) == 0) mw[tid >> 5] = bal;
        __syncthreads();

        if (wg == 0) {
            if (tid == 0) {
                int nm = 0;
                for (int w = 0; w < 16; w++) nm += __popc(mw[w]);
                g_nu[bt] = SSQ - nm;
            }
            if (tid < 16) g_maskw[bt*16 + tid] = mw[tid];
        }

        float qx = cs[tid*3], qy = cs[tid*3+1], qz = cs[tid*3+2];
        for (int w = wg*4; w < wg*4 + 4; w++) {
            unsigned bits = 0, mk = mw[w];
            #pragma unroll
            for (int bb = 0; bb < 32; bb++) {
                int j = w*32 + bb;
                float dx = qx - cs[j*3], dy = qy - cs[j*3+1], dz = qz - cs[j*3+2];
                float d2 = dx*dx + dy*dy + dz*dz;
                if (d2 < 625.0f && !((mk >> bb) & 1u)) bits |= (1u << bb);
            }
            g_bits[((size_t)bt*16 + w)*SSQ + tid] = bits;
        }
    } else if (bid < PRO_GATE + PRO_PREP) {
        // ---- weight tf32-round + within-16-group k-permute ----
        int g = (bid - PRO_GATE) * 512 + tid;
        if (g >= NGRP_TOT) return;
        const float* src; float* dst; int lg = g;
        if      (g <  NGRP_PROJ)            { src = Wq; dst = rWq; }
        else if (g < 2*NGRP_PROJ)           { src = Wk; dst = rWk; lg = g - NGRP_PROJ; }
        else if (g < 3*NGRP_PROJ)           { src = Wv; dst = rWv; lg = g - 2*NGRP_PROJ; }
        else if (g < 4*NGRP_PROJ)           { src = Wo; dst = rWo; lg = g - 3*NGRP_PROJ; }
        else if (g < 4*NGRP_PROJ+NGRP_FFN)  { src = W1; dst = rW1; lg = g - 4*NGRP_PROJ; }
        else                                { src = W2; dst = rW2; lg = g - 4*NGRP_PROJ - NGRP_FFN; }
        size_t base = (size_t)lg * 16;
        float v[16];
        #pragma unroll
        for (int j = 0; j < 16; j++) v[j] = src[base + j];
        #pragma unroll
        for (int p = 0; p < 16; p++) dst[base + p] = tfr(v[(p & 3) * 4 + (p >> 2)]);
    } else {
        // ---- qkenc = tfr(encoder + pos) ----
        int i = (bid - PRO_GATE - PRO_PREP) * 512 + tid;
        float4 av = ((const float4*)enc)[i];
        float4 bv = ((const float4*)pos)[i];
        float4 ov;
        ov.x = tfr(av.x + bv.x); ov.y = tfr(av.y + bv.y);
        ov.z = tfr(av.z + bv.z); ov.w = tfr(av.w + bv.w);
        ((float4*)qkenc)[i] = ov;
    }
}

// ---------------- fast LayerNorm (R9 measured-best: 256 thr, 16xf4/thread) ---
template<bool ADDPOS>
__global__ __launch_bounds__(256)
void ln_fast(const float* __restrict__ x,
             const float* __restrict__ gamma,
             const float* __restrict__ beta,
             float* __restrict__ y,
             const float* __restrict__ pos,
             float* __restrict__ y2)
{
    __shared__ float red_s[16][64];
    __shared__ float red_q[16][64];
    __shared__ float mu[64], rs[64];

    const int tid = threadIdx.x;
    const int c16 = tid >> 4;
    const int pg  = tid & 15;
    const int p0  = blockIdx.x * 64 + pg * 4;
    const int b   = p0 / TSZ;
    const int pi  = p0 - b * TSZ;
    const float* xb = x + (size_t)b * CC * TSZ + pi;

    float4 v[16];
    float4 s = make_float4(0.f,0.f,0.f,0.f), q = make_float4(0.f,0.f,0.f,0.f);
    #pragma unroll
    for (int i = 0; i < 16; i++) {
        v[i] = *(const float4*)(xb + (size_t)(c16*16 + i) * TSZ);
        s.x += v[i].x; s.y += v[i].y; s.z += v[i].z; s.w += v[i].w;
        q.x += v[i].x*v[i].x; q.y += v[i].y*v[i].y;
        q.z += v[i].z*v[i].z; q.w += v[i].w*v[i].w;
    }
    red_s[c16][pg*4+0] = s.x; red_s[c16][pg*4+1] = s.y;
    red_s[c16][pg*4+2] = s.z; red_s[c16][pg*4+3] = s.w;
    red_q[c16][pg*4+0] = q.x; red_q[c16][pg*4+1] = q.y;
    red_q[c16][pg*4+2] = q.z; red_q[c16][pg*4+3] = q.w;
    __syncthreads();

    if (tid < 64) {
        float ts = 0.f, tq = 0.f;
        #pragma unroll
        for (int k = 0; k < 16; k++) { ts += red_s[k][tid]; tq += red_q[k][tid]; }
        float m   = ts * (1.0f/CC);
        float var = tq * (1.0f/CC) - m*m;
        mu[tid] = m;
        rs[tid] = rsqrtf(var + 1e-5f);
    }
    __syncthreads();

    float4 m4 = *(const float4*)(mu + pg*4);
    float4 r4 = *(const float4*)(rs + pg*4);
    size_t off = (size_t)b * CC * TSZ + pi;

    #pragma unroll
    for (int i = 0; i < 16; i++) {
        const int c = c16*16 + i;
        const float g = __ldg(&gamma[c]), be = __ldg(&beta[c]);
        float4 nv;
        nv.x = tfr((v[i].x - m4.x) * r4.x * g + be);
        nv.y = tfr((v[i].y - m4.y) * r4.y * g + be);
        nv.z = tfr((v[i].z - m4.z) * r4.z * g + be);
        nv.w = tfr((v[i].w - m4.w) * r4.w * g + be);
        *(float4*)(y + off + (size_t)c * TSZ) = nv;
        if (ADDPOS) {
            float4 pv = *(const float4*)(pos + off + (size_t)c * TSZ);
            float4 ov;
            ov.x = tfr(nv.x + pv.x); ov.y = tfr(nv.y + pv.y);
            ov.z = tfr(nv.z + pv.z); ov.w = tfr(nv.w + pv.w);
            *(float4*)(y2 + off + (size_t)c * TSZ) = ov;
        }
    }
}

// ---------------- cp.async TF32 GEMM, tile 64x128x16, 3-stage, 3 CTAs/SM -----
// (R9 configuration verbatim — empirically fastest.)
// MODE bit0:+bias  bit1:relu  bit2:+=residual(Y)  bit3:tf32-round out
//      bit4:+residual from separate pointer Rb
#define GSTAGES 3
#define A_STG (64*16)
#define B_STG (16*136)
#define GEMM_SMEM ((GSTAGES*(A_STG+B_STG))*4)

__device__ __forceinline__ void cpa16(uint32_t s, const float* g) {
    asm volatile("cp.async.cg.shared.global [%0], [%1], 16;\n" :: "r"(s), "l"(g));
}

template<int MODE>
__device__ __forceinline__ void gemm_core(const float* __restrict__ Wb,
                                          const float* __restrict__ bias, int biasRow,
                                          const float* __restrict__ Xb,
                                          float* __restrict__ Yb,
                                          const float* __restrict__ Rb, int K)
{
    extern __shared__ float sm_[];
    float* As = sm_;
    float* Bs = sm_ + GSTAGES*A_STG;

    const int tid  = threadIdx.x;
    const int lane = tid & 31;
    const int gid  = lane >> 2;
    const int tig  = lane & 3;
    const int warp = tid >> 5;
    const int wm = (warp & 1) * 32;
    const int wn = (warp >> 1) * 32;

    const int arow = tid >> 2, akc = (tid & 3) * 4;
    const int bkr  = tid >> 4, bnc = (tid & 15) * 8;

    const uint32_t asb = (uint32_t)__cvta_generic_to_shared(As + arow*16 + akc);
    const uint32_t bsb = (uint32_t)__cvta_generic_to_shared(Bs + bkr*136 + bnc);
    const float* ag0 = Wb + (size_t)arow * K + akc;
    const float* bg0 = Xb + (size_t)bkr * TSZ + bnc;

    float acc[2][4][4];
    #pragma unroll
    for (int mi = 0; mi < 2; mi++)
        #pragma unroll
        for (int nj = 0; nj < 4; nj++)
            #pragma unroll
            for (int r = 0; r < 4; r++) acc[mi][nj][r] = 0.f;

    const int nIter = K / 16;

    #pragma unroll
    for (int s = 0; s < GSTAGES - 1; s++) {
        cpa16(asb + s*A_STG*4, ag0 + s*16);
        cpa16(bsb + s*B_STG*4,      bg0 + (size_t)s*16*TSZ);
        cpa16(bsb + s*B_STG*4 + 16, bg0 + (size_t)s*16*TSZ + 4);
        asm volatile("cp.async.commit_group;" ::: "memory");
    }

    for (int it = 0; it < nIter; ++it) {
        asm volatile("cp.async.wait_group 1;" ::: "memory");
        __syncthreads();

        if (it + GSTAGES - 1 < nIter) {
            const int s  = (it + GSTAGES - 1) % GSTAGES;
            const int k0 = (it + GSTAGES - 1) * 16;
            cpa16(asb + s*A_STG*4, ag0 + k0);
            cpa16(bsb + s*B_STG*4,      bg0 + (size_t)k0*TSZ);
            cpa16(bsb + s*B_STG*4 + 16, bg0 + (size_t)k0*TSZ + 4);
        }
        asm volatile("cp.async.commit_group;" ::: "memory");

        const float* Ab = As + (it % GSTAGES) * A_STG;
        const float* Bb = Bs + (it % GSTAGES) * B_STG;

        float4 af[4];
        #pragma unroll
        for (int j = 0; j < 4; j++)
            af[j] = *(const float4*)(Ab + (wm + j*8 + gid)*16 + tig*4);

        #pragma unroll
        for (int kk = 0; kk < 2; kk++) {
            uint32_t b[4][2];
            #pragma unroll
            for (int nj = 0; nj < 4; nj++) {
                const int c = wn + nj * 8 + gid;
                b[nj][0] = __float_as_uint(Bb[(kk*8 + tig)*136 + c]);
                b[nj][1] = __float_as_uint(Bb[(kk*8 + tig + 4)*136 + c]);
            }
            #pragma unroll
            for (int mi = 0; mi < 2; mi++) {
                uint32_t a0, a1, a2, a3;
                if (kk == 0) {
                    a0 = __float_as_uint(af[2*mi].x);   a1 = __float_as_uint(af[2*mi+1].x);
                    a2 = __float_as_uint(af[2*mi].y);   a3 = __float_as_uint(af[2*mi+1].y);
                } else {
                    a0 = __float_as_uint(af[2*mi].z);   a1 = __float_as_uint(af[2*mi+1].z);
                    a2 = __float_as_uint(af[2*mi].w);   a3 = __float_as_uint(af[2*mi+1].w);
                }
                #pragma unroll
                for (int nj = 0; nj < 4; nj++) {
                    asm volatile(
                        "mma.sync.aligned.m16n8k8.row.col.f32.tf32.tf32.f32 "
                        "{%0,%1,%2,%3}, {%4,%5,%6,%7}, {%8,%9}, {%0,%1,%2,%3};"
                        : "+f"(acc[mi][nj][0]), "+f"(acc[mi][nj][1]),
                          "+f"(acc[mi][nj][2]), "+f"(acc[mi][nj][3])
                        : "r"(a0), "r"(a1), "r"(a2), "r"(a3),
                          "r"(b[nj][0]), "r"(b[nj][1]));
                }
            }
        }
        __syncthreads();
    }

    #pragma unroll
    for (int mi = 0; mi < 2; mi++) {
        const int r0 = wm + mi * 16 + gid;
        float bia0 = 0.f, bia1 = 0.f;
        if (MODE & 1) {
            bia0 = __ldg(&bias[biasRow + r0]);
            bia1 = __ldg(&bias[biasRow + r0 + 8]);
        }
        #pragma unroll
        for (int nj = 0; nj < 4; nj++) {
            const int c = wn + nj * 8 + tig * 2;
            float2 v0 = make_float2(acc[mi][nj][0] + bia0, acc[mi][nj][1] + bia0);
            float2 v1 = make_float2(acc[mi][nj][2] + bia1, acc[mi][nj][3] + bia1);
            if (MODE & 2) {
                v0.x = fmaxf(v0.x, 0.f); v0.y = fmaxf(v0.y, 0.f);
                v1.x = fmaxf(v1.x, 0.f); v1.y = fmaxf(v1.y, 0.f);
            }
            if (MODE & 8) {
                v0.x = tfr(v0.x); v0.y = tfr(v0.y);
                v1.x = tfr(v1.x); v1.y = tfr(v1.y);
            }
            float* p0 = Yb + (size_t)r0 * TSZ + c;
            float* p1 = Yb + (size_t)(r0 + 8) * TSZ + c;
            if (MODE & 4) {
                float2 o0 = *(const float2*)p0;
                float2 o1 = *(const float2*)p1;
                v0.x += o0.x; v0.y += o0.y;
                v1.x += o1.x; v1.y += o1.y;
            }
            if (MODE & 16) {
                const float* q0 = Rb + (size_t)r0 * TSZ + c;
                const float* q1 = Rb + (size_t)(r0 + 8) * TSZ + c;
                float2 o0 = *(const float2*)q0;
                float2 o1 = *(const float2*)q1;
                v0.x += o0.x; v0.y += o0.y;
                v1.x += o1.x; v1.y += o1.y;
            }
            *(float2*)p0 = v0;
            *(float2*)p1 = v1;
        }
    }
}

template<int MODE>
__global__ __launch_bounds__(256, 3)
void gemm_ca(const float* __restrict__ W, const float* __restrict__ bias,
             const float* __restrict__ X, float* __restrict__ Y,
             const float* __restrict__ R, int M, int K)
{
    const int bx = blockIdx.x, by = blockIdx.y, bz = blockIdx.z;
    size_t off = (size_t)bz * M * TSZ + (size_t)by * 64 * TSZ + bx * 128;
    gemm_core<MODE>(W + (size_t)by * 64 * K, bias, by * 64,
                    X + (size_t)bz * K * TSZ + bx * 128,
                    Y + off, (MODE & 16) ? (R + off) : (const float*)nullptr, K);
}

__global__ __launch_bounds__(256, 3)
void gemm_qkv(const float* __restrict__ Wq, const float* __restrict__ Wk,
              const float* __restrict__ Wv,
              const float* __restrict__ bq, const float* __restrict__ bk,
              const float* __restrict__ bv,
              const float* __restrict__ Xqk, const float* __restrict__ Xv,
              float* __restrict__ Yq, float* __restrict__ Yk, float* __restrict__ Yv)
{
    const int bx = blockIdx.x, by = blockIdx.y, bz = blockIdx.z;
    const int seg = by >> 2, tile = by & 3;
    const float* W  = (seg == 0) ? Wq : (seg == 1) ? Wk : Wv;
    const float* bi = (seg == 0) ? bq : (seg == 1) ? bk : bv;
    const float* X  = (seg < 2) ? Xqk : Xv;
    float*       Y  = (seg == 0) ? Yq : (seg == 1) ? Yk : Yv;
    gemm_core<1>(W + (size_t)tile * 64 * CC, bi, tile * 64,
                 X + (size_t)bz * CC * TSZ + bx * 128,
                 Y + (size_t)bz * CC * TSZ + (size_t)tile * 64 * TSZ + bx * 128,
                 nullptr, CC);
}

// ---------------- sparse attention: single-pass online with zero anchor ------
#define KPAD 36
#define ATTN_SMEM_BYTES ((SSQ*KPAD*2 + 16*33 + 32)*4)

__global__ __launch_bounds__(512, 1)
void attn_sparse(const float* __restrict__ Q, const float* __restrict__ Kg,
                 const float* __restrict__ V, float* __restrict__ out)
{
    extern __shared__ float sm[];
    float* Ks = sm;
    float* Vs = Ks + SSQ*KPAD;
    float* partial = Vs + SSQ*KPAD;
    float* Vsum    = partial + 16*33;
    __shared__ unsigned mw[16];

    int blk = blockIdx.x;
    int b = blk / (HH*TT);
    int rem = blk - b*(HH*TT);
    int h = rem / TT;
    int t = rem - h*TT;
    int bt = b*TT + t;
    int tid = threadIdx.x;
    size_t base = ((size_t)(b*CC + h*HDIM))*TSZ + (size_t)t*SSQ;

    // preload all 16 bitmask words (independent loads, MLP=16)
    unsigned bw[16];
    const unsigned* bptr = g_bits + (size_t)bt*16*SSQ + tid;
    #pragma unroll
    for (int w = 0; w < 16; w++) bw[w] = __ldg(bptr + w*SSQ);

    #pragma unroll
    for (int d = 0; d < HDIM; d++) {
        Ks[tid*KPAD + d] = Kg[base + (size_t)d*TSZ + tid];
        Vs[tid*KPAD + d] = V [base + (size_t)d*TSZ + tid];
    }
    if (tid < 16) mw[tid] = g_maskw[bt*16 + tid];
    __syncthreads();

    {
        int d = tid & 31, c = tid >> 5;
        unsigned mk = mw[c];
        float s = 0.f;
        #pragma unroll 8
        for (int jj = 0; jj < 32; jj++)
            if (!((mk >> jj) & 1u)) s += Vs[(c*32 + jj)*KPAD + d];
        partial[c*33 + d] = s;
    }
    __syncthreads();
    if (tid < 32) {
        float s = 0.f;
        #pragma unroll
        for (int c = 0; c < 16; c++) s += partial[c*33 + tid];
        Vsum[tid] = s;
    }
    int N_u = g_nu[bt];
    __syncthreads();

    float qv[HDIM];
    #pragma unroll
    for (int d = 0; d < HDIM; d++) qv[d] = Q[base + (size_t)d*TSZ + tid];

    const float SCL = 0.17677669529663687f;

    float m  = 0.f;
    float p0 = 1.f;
    float l  = (float)N_u;
    float acc[HDIM];
    #pragma unroll
    for (int d = 0; d < HDIM; d++) acc[d] = Vsum[d];

    for (int w = 0; w < 16; w++) {
        unsigned bz = bw[w];
        while (bz) {
            int j = w*32 + (__ffs(bz) - 1);
            bz &= bz - 1;
            const float4* k4 = (const float4*)(Ks + j*KPAD);
            float dot = 0.f;
            #pragma unroll
            for (int r = 0; r < 8; r++) {
                float4 kk = k4[r];
                dot += qv[4*r]*kk.x + qv[4*r+1]*kk.y + qv[4*r+2]*kk.z + qv[4*r+3]*kk.w;
            }
            float lg = dot * SCL;
            if (lg > m) {
                float sc = __expf(m - lg);
                l *= sc;
                #pragma unroll
                for (int d = 0; d < HDIM; d++) acc[d] *= sc;
                m = lg;
                p0 = __expf(-m);
            }
            float p = __expf(lg - m) - p0;
            l += p;
            const float4* v4 = (const float4*)(Vs + j*KPAD);
            #pragma unroll
            for (int r = 0; r < 8; r++) {
                float4 vv = v4[r];
                acc[4*r]   += p * vv.x;
                acc[4*r+1] += p * vv.y;
                acc[4*r+2] += p * vv.z;
                acc[4*r+3] += p * vv.w;
            }
        }
    }

    float inv = 1.f / l;
    #pragma unroll
    for (int d = 0; d < HDIM; d++)
        out[base + (size_t)d*TSZ + tid] = tfr(acc[d] * inv);
}

// ---------------- orchestration ---------------------------------------------
extern "C" void kernel_launch(void* const* d_in, const int* in_sizes, int n_in,
                              void* d_out, int out_size)
{
    const float* decoder = (const float*)d_in[0];
    const float* encoder = (const float*)d_in[1];
    const float* pos     = (const float*)d_in[2];
    const float* coord   = (const float*)d_in[3];
    const unsigned int* mask = (const unsigned int*)d_in[4];
    const float* Wq = (const float*)d_in[5];
    const float* bq = (const float*)d_in[6];
    const float* Wk = (const float*)d_in[7];
    const float* bk = (const float*)d_in[8];
    const float* Wv = (const float*)d_in[9];
    const float* bv = (const float*)d_in[10];
    const float* Wo = (const float*)d_in[11];
    const float* bo = (const float*)d_in[12];
    const float* W1 = (const float*)d_in[13];
    const float* b1 = (const float*)d_in[14];
    const float* W2 = (const float*)d_in[15];
    const float* b2 = (const float*)d_in[16];
    const float* lng = (const float*)d_in[17];
    const float* lnb = (const float*)d_in[18];
    float* out = (float*)d_out;

    float *src2, *qk, *qkenc, *qb, *kb, *vb, *vals, *hbuf;
    float *rWq, *rWk, *rWv, *rWo, *rW1, *rW2;
    cudaGetSymbolAddress((void**)&src2,  g_src2);
    cudaGetSymbolAddress((void**)&qk,    g_qk);
    cudaGetSymbolAddress((void**)&qkenc, g_qkenc);
    cudaGetSymbolAddress((void**)&qb,    g_qb);
    cudaGetSymbolAddress((void**)&kb,    g_kb);
    cudaGetSymbolAddress((void**)&vb,    g_vb);
    cudaGetSymbolAddress((void**)&vals,  g_vals);
    cudaGetSymbolAddress((void**)&hbuf,  g_h);
    cudaGetSymbolAddress((void**)&rWq,   g_rWq);
    cudaGetSymbolAddress((void**)&rWk,   g_rWk);
    cudaGetSymbolAddress((void**)&rWv,   g_rWv);
    cudaGetSymbolAddress((void**)&rWo,   g_rWo);
    cudaGetSymbolAddress((void**)&rW1,   g_rW1);
    cudaGetSymbolAddress((void**)&rW2,   g_rW2);

    cudaFuncSetAttribute((const void*)attn_sparse,
                         cudaFuncAttributeMaxDynamicSharedMemorySize, ATTN_SMEM_BYTES);
    cudaFuncSetAttribute((const void*)gemm_qkv,
                         cudaFuncAttributeMaxDynamicSharedMemorySize, GEMM_SMEM);
    cudaFuncSetAttribute((const void*)gemm_ca<5>,
                         cudaFuncAttributeMaxDynamicSharedMemorySize, GEMM_SMEM);
    cudaFuncSetAttribute((const void*)gemm_ca<11>,
                         cudaFuncAttributeMaxDynamicSharedMemorySize, GEMM_SMEM);
    cudaFuncSetAttribute((const void*)gemm_ca<17>,
                         cudaFuncAttributeMaxDynamicSharedMemorySize, GEMM_SMEM);

    // fused prologue: gate bits + weight prep + (enc+pos), all concurrent
    prologue_kernel<<<PRO_BLOCKS, 512>>>(coord, mask,
                                         Wq, Wk, Wv, Wo, W1, W2,
                                         rWq, rWk, rWv, rWo, rW1, rW2,
                                         encoder, pos, qkenc);

    dim3 gqkv(TSZ/128, 12, BB);
    dim3 gp(TSZ/128, CC/64, BB);
    dim3 gf(TSZ/128, DFFN/64, BB);
    dim3 lnGrid(NPOS/64);               // 256 CTAs x 256 thr
    int  attnBlocks = BB * HH * TT;

    for (int i = 0; i < 2; i++) {
        const float* rWq_l = rWq + (size_t)i*CC*CC;   const float* bq_l = bq + (size_t)i*CC;
        const float* rWk_l = rWk + (size_t)i*CC*CC;   const float* bk_l = bk + (size_t)i*CC;
        const float* rWv_l = rWv + (size_t)i*CC*CC;   const float* bv_l = bv + (size_t)i*CC;
        const float* rWo_l = rWo + (size_t)i*CC*CC;   const float* bo_l = bo + (size_t)i*CC;
        const float* rW1_l = rW1 + (size_t)i*DFFN*CC; const float* b1_l = b1 + (size_t)i*DFFN;
        const float* rW2_l = rW2 + (size_t)i*CC*DFFN; const float* b2_l = b2 + (size_t)i*CC;
        const float* g0 = lng + (size_t)(i*3+0)*CC; const float* be0 = lnb + (size_t)(i*3+0)*CC;
        const float* g1 = lng + (size_t)(i*3+1)*CC; const float* be1 = lnb + (size_t)(i*3+1)*CC;
        const float* g2 = lng + (size_t)(i*3+2)*CC; const float* be2 = lnb + (size_t)(i*3+2)*CC;

        // ---- block 1: q/k = LN(dec)+pos (fused), v = LN(dec) ----
        const float* resid_in = (i == 0) ? decoder : out;
        ln_fast<true><<<lnGrid, 256>>>(resid_in, g0, be0, src2, pos, qk);
        gemm_qkv<<<gqkv, 256, GEMM_SMEM>>>(rWq_l, rWk_l, rWv_l, bq_l, bk_l, bv_l,
                                           qk, src2, qb, kb, vb);
        attn_sparse<<<attnBlocks, 512, ATTN_SMEM_BYTES>>>(qb, kb, vb, vals);
        if (i == 0)
            gemm_ca<17><<<gp, 256, GEMM_SMEM>>>(rWo_l, bo_l, vals, out, decoder, CC, CC);
        else
            gemm_ca<5><<<gp, 256, GEMM_SMEM>>>(rWo_l, bo_l, vals, out, nullptr, CC, CC);

        // ---- block 2: q/k = encoder+pos, v = LN(dec) ----
        ln_fast<false><<<lnGrid, 256>>>(out, g1, be1, src2, nullptr, nullptr);
        gemm_qkv<<<gqkv, 256, GEMM_SMEM>>>(rWq_l, rWk_l, rWv_l, bq_l, bk_l, bv_l,
                                           qkenc, src2, qb, kb, vb);
        attn_sparse<<<attnBlocks, 512, ATTN_SMEM_BYTES>>>(qb, kb, vb, vals);
        gemm_ca<5><<<gp, 256, GEMM_SMEM>>>(rWo_l, bo_l, vals, out, nullptr, CC, CC);

        // ---- FFN ----
        ln_fast<false><<<lnGrid, 256>>>(out, g2, be2, src2, nullptr, nullptr);
        gemm_ca<11><<<gf, 256, GEMM_SMEM>>>(rW1_l, b1_l, src2, hbuf, nullptr, DFFN, CC);
        gemm_ca<5><<<gp, 256, GEMM_SMEM>>>(rW2_l, b2_l, hbuf, out, nullptr, CC, DFFN);
    }
}

// round 15
// speedup vs baseline: 1.5590x; 1.0056x over previous
#include <cuda_runtime.h>
#include <cstdint>
#include <math.h>

// ---------------- problem constants ----------------
#define BB   2
#define CC   256
#define HH   8
#define HDIM 32
#define TT   16
#define SSQ  512
#define DFFN 1024
#define TSZ  (TT*SSQ)          // 8192
#define ACTN (BB*CC*TSZ)       // 4,194,304 floats
#define NPOS (BB*TSZ)          // 16384 positions

// ---------------- scratch ----------------------------------------------------
__device__ float g_src2[ACTN];
__device__ float g_qk[ACTN];
__device__ float g_qkenc[ACTN];
__device__ float g_qb[ACTN];
__device__ float g_kb[ACTN];
__device__ float g_vb[ACTN];
__device__ float g_vals[ACTN];
__device__ float g_h[BB*DFFN*TSZ];

// pre-rounded + k-permuted weights
__device__ float g_rWq[2*CC*CC];
__device__ float g_rWk[2*CC*CC];
__device__ float g_rWv[2*CC*CC];
__device__ float g_rWo[2*CC*CC];
__device__ float g_rW1[2*DFFN*CC];
__device__ float g_rW2[2*CC*DFFN];

// sparse-attention precompute: compacted active-key index lists
__device__ unsigned short g_lst[(size_t)BB*TT*SSQ*SSQ + SSQ];  // [bt][i][q] (+pad)
__device__ int      g_nact[BB*TT*SSQ];
__device__ unsigned g_maskw[BB*TT*16];
__device__ int      g_nu[BB*TT];

__device__ __forceinline__ uint32_t f2tf(float x) {
    uint32_t u;
    asm("cvt.rna.tf32.f32 %0, %1;" : "=r"(u) : "f"(x));
    return u;
}
__device__ __forceinline__ float tfr(float x) { return __uint_as_float(f2tf(x)); }

// ---------------- fused prologue: gate lists + weight prep + (enc+pos) -------
// block ranges: [0,32)        -> gate+list (one bt per block, 512 thr = queries)
//               [32,32+192)   -> weight round+permute (512 grp/blk)
//               [224,224+2048)-> qkenc = tfr(encoder+pos) (512 f4/blk)
#define NGRP_PROJ (2*CC*CC/16)
#define NGRP_FFN  (2*DFFN*CC/16)
#define NGRP_TOT  (4*NGRP_PROJ + 2*NGRP_FFN)      // 98304 = 192*512
#define PRO_GATE   32
#define PRO_PREP   192
#define PRO_ADD    (ACTN/4/512)                   // 2048
#define PRO_BLOCKS (PRO_GATE + PRO_PREP + PRO_ADD)

__global__ __launch_bounds__(512)
void prologue_kernel(const float* __restrict__ coord,
                     const unsigned* __restrict__ mask,
                     const float* __restrict__ Wq, const float* __restrict__ Wk,
                     const float* __restrict__ Wv, const float* __restrict__ Wo,
                     const float* __restrict__ W1, const float* __restrict__ W2,
                     float* __restrict__ rWq, float* __restrict__ rWk,
                     float* __restrict__ rWv, float* __restrict__ rWo,
                     float* __restrict__ rW1, float* __restrict__ rW2,
                     const float* __restrict__ enc, const float* __restrict__ pos,
                     float* __restrict__ qkenc)
{
    const int bid = blockIdx.x;
    const int tid = threadIdx.x;

    if (bid < PRO_GATE) {
        // ---- gate: per-query compacted active-key list (active = gated & unmasked)
        __shared__ float cs[SSQ*3];
        __shared__ unsigned mw[16];
        int bt = bid;                          // 0..31

        size_t cbase = (size_t)bt * SSQ * 3;
        for (int i = tid; i < SSQ*3; i += 512) cs[i] = coord[cbase + i];
        unsigned mv  = (mask[(size_t)bt*SSQ + tid] != 0u);
        unsigned bal = __ballot_sync(0xffffffffu, mv);
        if ((tid & 31) == 0) mw[tid >> 5] = bal;
        __syncthreads();

        if (tid == 0) {
            int nm = 0;
            for (int w = 0; w < 16; w++) nm += __popc(mw[w]);
            g_nu[bt] = SSQ - nm;
        }
        if (tid < 16) g_maskw[bt*16 + tid] = mw[tid];

        float qx = cs[tid*3], qy = cs[tid*3+1], qz = cs[tid*3+2];
        unsigned short* lq = g_lst + (size_t)bt*SSQ*SSQ + tid;
        int n = 0;
        for (int w = 0; w < 16; w++) {
            unsigned mk = mw[w];
            #pragma unroll 8
            for (int bb = 0; bb < 32; bb++) {
                int j = w*32 + bb;
                float dx = qx - cs[j*3], dy = qy - cs[j*3+1], dz = qz - cs[j*3+2];
                float d2 = dx*dx + dy*dy + dz*dz;
                if (d2 < 625.0f && !((mk >> bb) & 1u)) {
                    lq[(size_t)n * SSQ] = (unsigned short)j;
                    n++;
                }
            }
        }
        g_nact[bt*SSQ + tid] = n;
    } else if (bid < PRO_GATE + PRO_PREP) {
        // ---- weight tf32-round + within-16-group k-permute ----
        int g = (bid - PRO_GATE) * 512 + tid;
        if (g >= NGRP_TOT) return;
        const float* src; float* dst; int lg = g;
        if      (g <  NGRP_PROJ)            { src = Wq; dst = rWq; }
        else if (g < 2*NGRP_PROJ)           { src = Wk; dst = rWk; lg = g - NGRP_PROJ; }
        else if (g < 3*NGRP_PROJ)           { src = Wv; dst = rWv; lg = g - 2*NGRP_PROJ; }
        else if (g < 4*NGRP_PROJ)           { src = Wo; dst = rWo; lg = g - 3*NGRP_PROJ; }
        else if (g < 4*NGRP_PROJ+NGRP_FFN)  { src = W1; dst = rW1; lg = g - 4*NGRP_PROJ; }
        else                                { src = W2; dst = rW2; lg = g - 4*NGRP_PROJ - NGRP_FFN; }
        size_t base = (size_t)lg * 16;
        float v[16];
        #pragma unroll
        for (int j = 0; j < 16; j++) v[j] = src[base + j];
        #pragma unroll
        for (int p = 0; p < 16; p++) dst[base + p] = tfr(v[(p & 3) * 4 + (p >> 2)]);
    } else {
        // ---- qkenc = tfr(encoder + pos) ----
        int i = (bid - PRO_GATE - PRO_PREP) * 512 + tid;
        float4 av = ((const float4*)enc)[i];
        float4 bv = ((const float4*)pos)[i];
        float4 ov;
        ov.x = tfr(av.x + bv.x); ov.y = tfr(av.y + bv.y);
        ov.z = tfr(av.z + bv.z); ov.w = tfr(av.w + bv.w);
        ((float4*)qkenc)[i] = ov;
    }
}

// ---------------- fast LayerNorm (256 thr, 16xf4/thread — measured best) -----
template<bool ADDPOS>
__global__ __launch_bounds__(256)
void ln_fast(const float* __restrict__ x,
             const float* __restrict__ gamma,
             const float* __restrict__ beta,
             float* __restrict__ y,
             const float* __restrict__ pos,
             float* __restrict__ y2)
{
    __shared__ float red_s[16][64];
    __shared__ float red_q[16][64];
    __shared__ float mu[64], rs[64];

    const int tid = threadIdx.x;
    const int c16 = tid >> 4;
    const int pg  = tid & 15;
    const int p0  = blockIdx.x * 64 + pg * 4;
    const int b   = p0 / TSZ;
    const int pi  = p0 - b * TSZ;
    const float* xb = x + (size_t)b * CC * TSZ + pi;

    float4 v[16];
    float4 s = make_float4(0.f,0.f,0.f,0.f), q = make_float4(0.f,0.f,0.f,0.f);
    #pragma unroll
    for (int i = 0; i < 16; i++) {
        v[i] = *(const float4*)(xb + (size_t)(c16*16 + i) * TSZ);
        s.x += v[i].x; s.y += v[i].y; s.z += v[i].z; s.w += v[i].w;
        q.x += v[i].x*v[i].x; q.y += v[i].y*v[i].y;
        q.z += v[i].z*v[i].z; q.w += v[i].w*v[i].w;
    }
    red_s[c16][pg*4+0] = s.x; red_s[c16][pg*4+1] = s.y;
    red_s[c16][pg*4+2] = s.z; red_s[c16][pg*4+3] = s.w;
    red_q[c16][pg*4+0] = q.x; red_q[c16][pg*4+1] = q.y;
    red_q[c16][pg*4+2] = q.z; red_q[c16][pg*4+3] = q.w;
    __syncthreads();

    if (tid < 64) {
        float ts = 0.f, tq = 0.f;
        #pragma unroll
        for (int k = 0; k < 16; k++) { ts += red_s[k][tid]; tq += red_q[k][tid]; }
        float m   = ts * (1.0f/CC);
        float var = tq * (1.0f/CC) - m*m;
        mu[tid] = m;
        rs[tid] = rsqrtf(var + 1e-5f);
    }
    __syncthreads();

    float4 m4 = *(const float4*)(mu + pg*4);
    float4 r4 = *(const float4*)(rs + pg*4);
    size_t off = (size_t)b * CC * TSZ + pi;

    #pragma unroll
    for (int i = 0; i < 16; i++) {
        const int c = c16*16 + i;
        const float g = __ldg(&gamma[c]), be = __ldg(&beta[c]);
        float4 nv;
        nv.x = tfr((v[i].x - m4.x) * r4.x * g + be);
        nv.y = tfr((v[i].y - m4.y) * r4.y * g + be);
        nv.z = tfr((v[i].z - m4.z) * r4.z * g + be);
        nv.w = tfr((v[i].w - m4.w) * r4.w * g + be);
        *(float4*)(y + off + (size_t)c * TSZ) = nv;
        if (ADDPOS) {
            float4 pv = *(const float4*)(pos + off + (size_t)c * TSZ);
            float4 ov;
            ov.x = tfr(nv.x + pv.x); ov.y = tfr(nv.y + pv.y);
            ov.z = tfr(nv.z + pv.z); ov.w = tfr(nv.w + pv.w);
            *(float4*)(y2 + off + (size_t)c * TSZ) = ov;
        }
    }
}

// ---------------- cp.async TF32 GEMM, tile 64x128x16, 3-stage, 3 CTAs/SM -----
// (R9/R14 configuration verbatim — empirically fastest.)
// MODE bit0:+bias  bit1:relu  bit2:+=residual(Y)  bit3:tf32-round out
//      bit4:+residual from separate pointer Rb
#define GSTAGES 3
#define A_STG (64*16)
#define B_STG (16*136)
#define GEMM_SMEM ((GSTAGES*(A_STG+B_STG))*4)

__device__ __forceinline__ void cpa16(uint32_t s, const float* g) {
    asm volatile("cp.async.cg.shared.global [%0], [%1], 16;\n" :: "r"(s), "l"(g));
}

template<int MODE>
__device__ __forceinline__ void gemm_core(const float* __restrict__ Wb,
                                          const float* __restrict__ bias, int biasRow,
                                          const float* __restrict__ Xb,
                                          float* __restrict__ Yb,
                                          const float* __restrict__ Rb, int K)
{
    extern __shared__ float sm_[];
    float* As = sm_;
    float* Bs = sm_ + GSTAGES*A_STG;

    const int tid  = threadIdx.x;
    const int lane = tid & 31;
    const int gid  = lane >> 2;
    const int tig  = lane & 3;
    const int warp = tid >> 5;
    const int wm = (warp & 1) * 32;
    const int wn = (warp >> 1) * 32;

    const int arow = tid >> 2, akc = (tid & 3) * 4;
    const int bkr  = tid >> 4, bnc = (tid & 15) * 8;

    const uint32_t asb = (uint32_t)__cvta_generic_to_shared(As + arow*16 + akc);
    const uint32_t bsb = (uint32_t)__cvta_generic_to_shared(Bs + bkr*136 + bnc);
    const float* ag0 = Wb + (size_t)arow * K + akc;
    const float* bg0 = Xb + (size_t)bkr * TSZ + bnc;

    float acc[2][4][4];
    #pragma unroll
    for (int mi = 0; mi < 2; mi++)
        #pragma unroll
        for (int nj = 0; nj < 4; nj++)
            #pragma unroll
            for (int r = 0; r < 4; r++) acc[mi][nj][r] = 0.f;

    const int nIter = K / 16;

    #pragma unroll
    for (int s = 0; s < GSTAGES - 1; s++) {
        cpa16(asb + s*A_STG*4, ag0 + s*16);
        cpa16(bsb + s*B_STG*4,      bg0 + (size_t)s*16*TSZ);
        cpa16(bsb + s*B_STG*4 + 16, bg0 + (size_t)s*16*TSZ + 4);
        asm volatile("cp.async.commit_group;" ::: "memory");
    }

    for (int it = 0; it < nIter; ++it) {
        asm volatile("cp.async.wait_group 1;" ::: "memory");
        __syncthreads();

        if (it + GSTAGES - 1 < nIter) {
            const int s  = (it + GSTAGES - 1) % GSTAGES;
            const int k0 = (it + GSTAGES - 1) * 16;
            cpa16(asb + s*A_STG*4, ag0 + k0);
            cpa16(bsb + s*B_STG*4,      bg0 + (size_t)k0*TSZ);
            cpa16(bsb + s*B_STG*4 + 16, bg0 + (size_t)k0*TSZ + 4);
        }
        asm volatile("cp.async.commit_group;" ::: "memory");

        const float* Ab = As + (it % GSTAGES) * A_STG;
        const float* Bb = Bs + (it % GSTAGES) * B_STG;

        float4 af[4];
        #pragma unroll
        for (int j = 0; j < 4; j++)
            af[j] = *(const float4*)(Ab + (wm + j*8 + gid)*16 + tig*4);

        #pragma unroll
        for (int kk = 0; kk < 2; kk++) {
            uint32_t b[4][2];
            #pragma unroll
            for (int nj = 0; nj < 4; nj++) {
                const int c = wn + nj * 8 + gid;
                b[nj][0] = __float_as_uint(Bb[(kk*8 + tig)*136 + c]);
                b[nj][1] = __float_as_uint(Bb[(kk*8 + tig + 4)*136 + c]);
            }
            #pragma unroll
            for (int mi = 0; mi < 2; mi++) {
                uint32_t a0, a1, a2, a3;
                if (kk == 0) {
                    a0 = __float_as_uint(af[2*mi].x);   a1 = __float_as_uint(af[2*mi+1].x);
                    a2 = __float_as_uint(af[2*mi].y);   a3 = __float_as_uint(af[2*mi+1].y);
                } else {
                    a0 = __float_as_uint(af[2*mi].z);   a1 = __float_as_uint(af[2*mi+1].z);
                    a2 = __float_as_uint(af[2*mi].w);   a3 = __float_as_uint(af[2*mi+1].w);
                }
                #pragma unroll
                for (int nj = 0; nj < 4; nj++) {
                    asm volatile(
                        "mma.sync.aligned.m16n8k8.row.col.f32.tf32.tf32.f32 "
                        "{%0,%1,%2,%3}, {%4,%5,%6,%7}, {%8,%9}, {%0,%1,%2,%3};"
                        : "+f"(acc[mi][nj][0]), "+f"(acc[mi][nj][1]),
                          "+f"(acc[mi][nj][2]), "+f"(acc[mi][nj][3])
                        : "r"(a0), "r"(a1), "r"(a2), "r"(a3),
                          "r"(b[nj][0]), "r"(b[nj][1]));
                }
            }
        }
        __syncthreads();
    }

    #pragma unroll
    for (int mi = 0; mi < 2; mi++) {
        const int r0 = wm + mi * 16 + gid;
        float bia0 = 0.f, bia1 = 0.f;
        if (MODE & 1) {
            bia0 = __ldg(&bias[biasRow + r0]);
            bia1 = __ldg(&bias[biasRow + r0 + 8]);
        }
        #pragma unroll
        for (int nj = 0; nj < 4; nj++) {
            const int c = wn + nj * 8 + tig * 2;
            float2 v0 = make_float2(acc[mi][nj][0] + bia0, acc[mi][nj][1] + bia0);
            float2 v1 = make_float2(acc[mi][nj][2] + bia1, acc[mi][nj][3] + bia1);
            if (MODE & 2) {
                v0.x = fmaxf(v0.x, 0.f); v0.y = fmaxf(v0.y, 0.f);
                v1.x = fmaxf(v1.x, 0.f); v1.y = fmaxf(v1.y, 0.f);
            }
            if (MODE & 8) {
                v0.x = tfr(v0.x); v0.y = tfr(v0.y);
                v1.x = tfr(v1.x); v1.y = tfr(v1.y);
            }
            float* p0 = Yb + (size_t)r0 * TSZ + c;
            float* p1 = Yb + (size_t)(r0 + 8) * TSZ + c;
            if (MODE & 4) {
                float2 o0 = *(const float2*)p0;
                float2 o1 = *(const float2*)p1;
                v0.x += o0.x; v0.y += o0.y;
                v1.x += o1.x; v1.y += o1.y;
            }
            if (MODE & 16) {
                const float* q0 = Rb + (size_t)r0 * TSZ + c;
                const float* q1 = Rb + (size_t)(r0 + 8) * TSZ + c;
                float2 o0 = *(const float2*)q0;
                float2 o1 = *(const float2*)q1;
                v0.x += o0.x; v0.y += o0.y;
                v1.x += o1.x; v1.y += o1.y;
            }
            *(float2*)p0 = v0;
            *(float2*)p1 = v1;
        }
    }
}

template<int MODE>
__global__ __launch_bounds__(256, 3)
void gemm_ca(const float* __restrict__ W, const float* __restrict__ bias,
             const float* __restrict__ X, float* __restrict__ Y,
             const float* __restrict__ R, int M, int K)
{
    const int bx = blockIdx.x, by = blockIdx.y, bz = blockIdx.z;
    size_t off = (size_t)bz * M * TSZ + (size_t)by * 64 * TSZ + bx * 128;
    gemm_core<MODE>(W + (size_t)by * 64 * K, bias, by * 64,
                    X + (size_t)bz * K * TSZ + bx * 128,
                    Y + off, (MODE & 16) ? (R + off) : (const float*)nullptr, K);
}

__global__ __launch_bounds__(256, 3)
void gemm_qkv(const float* __restrict__ Wq, const float* __restrict__ Wk,
              const float* __restrict__ Wv,
              const float* __restrict__ bq, const float* __restrict__ bk,
              const float* __restrict__ bv,
              const float* __restrict__ Xqk, const float* __restrict__ Xv,
              float* __restrict__ Yq, float* __restrict__ Yk, float* __restrict__ Yv)
{
    const int bx = blockIdx.x, by = blockIdx.y, bz = blockIdx.z;
    const int seg = by >> 2, tile = by & 3;
    const float* W  = (seg == 0) ? Wq : (seg == 1) ? Wk : Wv;
    const float* bi = (seg == 0) ? bq : (seg == 1) ? bk : bv;
    const float* X  = (seg < 2) ? Xqk : Xv;
    float*       Y  = (seg == 0) ? Yq : (seg == 1) ? Yk : Yv;
    gemm_core<1>(W + (size_t)tile * 64 * CC, bi, tile * 64,
                 X + (size_t)bz * CC * TSZ + bx * 128,
                 Y + (size_t)bz * CC * TSZ + (size_t)tile * 64 * TSZ + bx * 128,
                 nullptr, CC);
}

// ---------------- sparse attention: fixed zero anchor + index lists ----------
// weights: ungated unmasked keys contribute e^0 = 1 (folded via N_u and Vsum);
// each active key corrects by p = e^{lg} - 1. Logits bounded (~|15|) -> no
// overflow; no max-tracking, no rescale chain.
#define KPAD 36
#define ATTN_SMEM_BYTES ((SSQ*KPAD*2 + 16*33 + 32)*4)

__global__ __launch_bounds__(512, 1)
void attn_sparse(const float* __restrict__ Q, const float* __restrict__ Kg,
                 const float* __restrict__ V, float* __restrict__ out)
{
    extern __shared__ float sm[];
    float* Ks = sm;
    float* Vs = Ks + SSQ*KPAD;
    float* partial = Vs + SSQ*KPAD;
    float* Vsum    = partial + 16*33;
    __shared__ unsigned mw[16];

    int blk = blockIdx.x;
    int b = blk / (HH*TT);
    int rem = blk - b*(HH*TT);
    int h = rem / TT;
    int t = rem - h*TT;
    int bt = b*TT + t;
    int tid = threadIdx.x;
    size_t base = ((size_t)(b*CC + h*HDIM))*TSZ + (size_t)t*SSQ;

    #pragma unroll
    for (int d = 0; d < HDIM; d++) {
        Ks[tid*KPAD + d] = Kg[base + (size_t)d*TSZ + tid];
        Vs[tid*KPAD + d] = V [base + (size_t)d*TSZ + tid];
    }
    if (tid < 16) mw[tid] = g_maskw[bt*16 + tid];
    __syncthreads();

    {
        int d = tid & 31, c = tid >> 5;
        unsigned mk = mw[c];
        float s = 0.f;
        #pragma unroll 8
        for (int jj = 0; jj < 32; jj++)
            if (!((mk >> jj) & 1u)) s += Vs[(c*32 + jj)*KPAD + d];
        partial[c*33 + d] = s;
    }
    __syncthreads();
    if (tid < 32) {
        float s = 0.f;
        #pragma unroll
        for (int c = 0; c < 16; c++) s += partial[c*33 + tid];
        Vsum[tid] = s;
    }
    int N_u = g_nu[bt];
    __syncthreads();

    float qv[HDIM];
    #pragma unroll
    for (int d = 0; d < HDIM; d++) qv[d] = Q[base + (size_t)d*TSZ + tid];

    const float SCL = 0.17677669529663687f;

    float l = (float)N_u;
    float acc[HDIM];
    #pragma unroll
    for (int d = 0; d < HDIM; d++) acc[d] = Vsum[d];

    const int n_act = g_nact[bt*SSQ + tid];
    const unsigned short* lst = g_lst + (size_t)bt*SSQ*SSQ + tid;

    int j = (n_act > 0) ? (int)__ldg(lst) : 0;
    for (int i = 0; i < n_act; i++) {
        int jn = (i + 1 < n_act) ? (int)__ldg(lst + (size_t)(i+1)*SSQ) : 0;

        const float4* k4 = (const float4*)(Ks + j*KPAD);
        float dot = 0.f;
        #pragma unroll
        for (int r = 0; r < 8; r++) {
            float4 kk = k4[r];
            dot += qv[4*r]*kk.x + qv[4*r+1]*kk.y + qv[4*r+2]*kk.z + qv[4*r+3]*kk.w;
        }
        float p = __expf(dot * SCL) - 1.0f;
        l += p;
        const float4* v4 = (const float4*)(Vs + j*KPAD);
        #pragma unroll
        for (int r = 0; r < 8; r++) {
            float4 vv = v4[r];
            acc[4*r]   += p * vv.x;
            acc[4*r+1] += p * vv.y;
            acc[4*r+2] += p * vv.z;
            acc[4*r+3] += p * vv.w;
        }
        j = jn;
    }

    float inv = 1.f / l;
    #pragma unroll
    for (int d = 0; d < HDIM; d++)
        out[base + (size_t)d*TSZ + tid] = tfr(acc[d] * inv);
}

// ---------------- orchestration ---------------------------------------------
extern "C" void kernel_launch(void* const* d_in, const int* in_sizes, int n_in,
                              void* d_out, int out_size)
{
    const float* decoder = (const float*)d_in[0];
    const float* encoder = (const float*)d_in[1];
    const float* pos     = (const float*)d_in[2];
    const float* coord   = (const float*)d_in[3];
    const unsigned int* mask = (const unsigned int*)d_in[4];
    const float* Wq = (const float*)d_in[5];
    const float* bq = (const float*)d_in[6];
    const float* Wk = (const float*)d_in[7];
    const float* bk = (const float*)d_in[8];
    const float* Wv = (const float*)d_in[9];
    const float* bv = (const float*)d_in[10];
    const float* Wo = (const float*)d_in[11];
    const float* bo = (const float*)d_in[12];
    const float* W1 = (const float*)d_in[13];
    const float* b1 = (const float*)d_in[14];
    const float* W2 = (const float*)d_in[15];
    const float* b2 = (const float*)d_in[16];
    const float* lng = (const float*)d_in[17];
    const float* lnb = (const float*)d_in[18];
    float* out = (float*)d_out;

    float *src2, *qk, *qkenc, *qb, *kb, *vb, *vals, *hbuf;
    float *rWq, *rWk, *rWv, *rWo, *rW1, *rW2;
    cudaGetSymbolAddress((void**)&src2,  g_src2);
    cudaGetSymbolAddress((void**)&qk,    g_qk);
    cudaGetSymbolAddress((void**)&qkenc, g_qkenc);
    cudaGetSymbolAddress((void**)&qb,    g_qb);
    cudaGetSymbolAddress((void**)&kb,    g_kb);
    cudaGetSymbolAddress((void**)&vb,    g_vb);
    cudaGetSymbolAddress((void**)&vals,  g_vals);
    cudaGetSymbolAddress((void**)&hbuf,  g_h);
    cudaGetSymbolAddress((void**)&rWq,   g_rWq);
    cudaGetSymbolAddress((void**)&rWk,   g_rWk);
    cudaGetSymbolAddress((void**)&rWv,   g_rWv);
    cudaGetSymbolAddress((void**)&rWo,   g_rWo);
    cudaGetSymbolAddress((void**)&rW1,   g_rW1);
    cudaGetSymbolAddress((void**)&rW2,   g_rW2);

    cudaFuncSetAttribute((const void*)attn_sparse,
                         cudaFuncAttributeMaxDynamicSharedMemorySize, ATTN_SMEM_BYTES);
    cudaFuncSetAttribute((const void*)gemm_qkv,
                         cudaFuncAttributeMaxDynamicSharedMemorySize, GEMM_SMEM);
    cudaFuncSetAttribute((const void*)gemm_ca<5>,
                         cudaFuncAttributeMaxDynamicSharedMemorySize, GEMM_SMEM);
    cudaFuncSetAttribute((const void*)gemm_ca<11>,
                         cudaFuncAttributeMaxDynamicSharedMemorySize, GEMM_SMEM);
    cudaFuncSetAttribute((const void*)gemm_ca<17>,
                         cudaFuncAttributeMaxDynamicSharedMemorySize, GEMM_SMEM);

    // fused prologue: gate lists + weight prep + (enc+pos), all concurrent
    prologue_kernel<<<PRO_BLOCKS, 512>>>(coord, mask,
                                         Wq, Wk, Wv, Wo, W1, W2,
                                         rWq, rWk, rWv, rWo, rW1, rW2,
                                         encoder, pos, qkenc);

    dim3 gqkv(TSZ/128, 12, BB);
    dim3 gp(TSZ/128, CC/64, BB);
    dim3 gf(TSZ/128, DFFN/64, BB);
    dim3 lnGrid(NPOS/64);               // 256 CTAs x 256 thr
    int  attnBlocks = BB * HH * TT;

    for (int i = 0; i < 2; i++) {
        const float* rWq_l = rWq + (size_t)i*CC*CC;   const float* bq_l = bq + (size_t)i*CC;
        const float* rWk_l = rWk + (size_t)i*CC*CC;   const float* bk_l = bk + (size_t)i*CC;
        const float* rWv_l = rWv + (size_t)i*CC*CC;   const float* bv_l = bv + (size_t)i*CC;
        const float* rWo_l = rWo + (size_t)i*CC*CC;   const float* bo_l = bo + (size_t)i*CC;
        const float* rW1_l = rW1 + (size_t)i*DFFN*CC; const float* b1_l = b1 + (size_t)i*DFFN;
        const float* rW2_l = rW2 + (size_t)i*CC*DFFN; const float* b2_l = b2 + (size_t)i*CC;
        const float* g0 = lng + (size_t)(i*3+0)*CC; const float* be0 = lnb + (size_t)(i*3+0)*CC;
        const float* g1 = lng + (size_t)(i*3+1)*CC; const float* be1 = lnb + (size_t)(i*3+1)*CC;
        const float* g2 = lng + (size_t)(i*3+2)*CC; const float* be2 = lnb + (size_t)(i*3+2)*CC;

        // ---- block 1: q/k = LN(dec)+pos (fused), v = LN(dec) ----
        const float* resid_in = (i == 0) ? decoder : out;
        ln_fast<true><<<lnGrid, 256>>>(resid_in, g0, be0, src2, pos, qk);
        gemm_qkv<<<gqkv, 256, GEMM_SMEM>>>(rWq_l, rWk_l, rWv_l, bq_l, bk_l, bv_l,
                                           qk, src2, qb, kb, vb);
        attn_sparse<<<attnBlocks, 512, ATTN_SMEM_BYTES>>>(qb, kb, vb, vals);
        if (i == 0)
            gemm_ca<17><<<gp, 256, GEMM_SMEM>>>(rWo_l, bo_l, vals, out, decoder, CC, CC);
        else
            gemm_ca<5><<<gp, 256, GEMM_SMEM>>>(rWo_l, bo_l, vals, out, nullptr, CC, CC);

        // ---- block 2: q/k = encoder+pos, v = LN(dec) ----
        ln_fast<false><<<lnGrid, 256>>>(out, g1, be1, src2, nullptr, nullptr);
        gemm_qkv<<<gqkv, 256, GEMM_SMEM>>>(rWq_l, rWk_l, rWv_l, bq_l, bk_l, bv_l,
                                           qkenc, src2, qb, kb, vb);
        attn_sparse<<<attnBlocks, 512, ATTN_SMEM_BYTES>>>(qb, kb, vb, vals);
        gemm_ca<5><<<gp, 256, GEMM_SMEM>>>(rWo_l, bo_l, vals, out, nullptr, CC, CC);

        // ---- FFN ----
        ln_fast<false><<<lnGrid, 256>>>(out, g2, be2, src2, nullptr, nullptr);
        gemm_ca<11><<<gf, 256, GEMM_SMEM>>>(rW1_l, b1_l, src2, hbuf, nullptr, DFFN, CC);
        gemm_ca<5><<<gp, 256, GEMM_SMEM>>>(rW2_l, b2_l, hbuf, out, nullptr, CC, DFFN);
    }
}